// round 5
// baseline (speedup 1.0000x reference)
#include <cuda_runtime.h>
#include <math.h>
#include <stdint.h>

// ---------------- scratch (static device memory; no allocs allowed) ----------
__device__ float g_conv[102760448];   // max stored conv out: 256*32*112*112 (411 MB)
__device__ float g_poolA[51380224];   // 256*16*112*112 (205 MB); also pool3 out (51 MB)
__device__ float g_poolB[25690112];   // 256*32*56*56  (103 MB)
__device__ float g_psum[3 * 64 * 512];
__device__ float g_psumsq[3 * 64 * 512];
__device__ float g_scale[64];
__device__ float g_shift[64];

// ---------------- packed f32x2 helpers ---------------------------------------
__device__ __forceinline__ unsigned long long pk2(float lo, float hi) {
    unsigned long long r;
    asm("mov.b64 %0, {%1, %2};" : "=l"(r) : "f"(lo), "f"(hi));
    return r;
}
__device__ __forceinline__ void upk2(float& lo, float& hi, unsigned long long v) {
    asm("mov.b64 {%0, %1}, %2;" : "=f"(lo), "=f"(hi) : "l"(v));
}
__device__ __forceinline__ unsigned long long fma2(unsigned long long a,
                                                   unsigned long long b,
                                                   unsigned long long c) {
    unsigned long long d;
    asm("fma.rn.f32x2 %0, %1, %2, %3;" : "=l"(d) : "l"(a), "l"(b), "l"(c));
    return d;
}

// ---------------- zero partial-stat buffers ----------------------------------
__global__ void zero_partials_k() {
    int i = blockIdx.x * blockDim.x + threadIdx.x;
    if (i < 3 * 64 * 512) { g_psum[i] = 0.f; g_psumsq[i] = 0.f; }
}

// ---------------- finalize: reduce partials -> scale/shift --------------------
__global__ void finalize_k(const float* __restrict__ gam, const float* __restrict__ bet,
                           int C, int layer, double inv_cnt) {
    int c = threadIdx.x;
    if (c < C) {
        const float* ps = &g_psum[(layer * 64 + c) * 512];
        const float* pq = &g_psumsq[(layer * 64 + c) * 512];
        double S = 0.0, Q = 0.0;
        for (int i = 0; i < 512; i++) { S += (double)ps[i]; Q += (double)pq[i]; }
        double mean = S * inv_cnt;
        double var = Q * inv_cnt - mean * mean;
        float sc = gam[c] * rsqrtf((float)var + 1e-5f);
        g_scale[c] = sc;
        g_shift[c] = bet[c] - sc * (float)mean;
    }
}

// ---------------- direct 3x3 conv with packed f32x2 FMA ----------------------
// Block = 128 threads. Tile = 32(x) x 16(y); each thread: 4 px (2 f32x2 pairs) x 16 co.
// Weights pre-duplicated (w,w) in smem -> 1 LDS.64 per tap. Double-buffered input.
template<int CI, bool STORE>
__launch_bounds__(128)
__global__ void conv3x3_k(const float* __restrict__ in, const float* __restrict__ w,
                          const float* __restrict__ bias, float* __restrict__ out,
                          int CO, int H, int W, int tiles_x, int layer) {
    __shared__ float s_in[2][18][35];
    __shared__ unsigned long long s_wd[CI * 16 * 9];   // duplicated weight pairs
    __shared__ float redS[16][4], redQ[16][4];
    const int n   = blockIdx.z;
    const int cog = blockIdx.y;            // group of 16 output channels
    const int tile = blockIdx.x;
    const int tx = tile % tiles_x, ty = tile / tiles_x;
    const int tid = threadIdx.x;
    const int warp = tid >> 5, lane = tid & 31;

    for (int i = tid; i < CI * 16 * 9; i += 128) {
        float wv = w[(size_t)(cog * 16) * CI * 9 + i];
        s_wd[i] = pk2(wv, wv);
    }

    const int px = (tid & 7) * 4;
    const int py = tid >> 3;
    const int gx0 = tx * 32 - 1;
    const int gy0 = ty * 16 - 1;
    const bool interior = (gx0 >= 0) && (gy0 >= 0) && (gx0 + 33 < W) && (gy0 + 17 < H);

    auto load_tile = [&](int ci, int b) {
        const float* ip = in + ((size_t)n * CI + ci) * (size_t)H * W;
        if (interior) {
            for (int i = tid; i < 18 * 34; i += 128) {
                int r = i / 34, c = i % 34;
                s_in[b][r][c] = ip[(size_t)(gy0 + r) * W + (gx0 + c)];
            }
        } else {
            for (int i = tid; i < 18 * 34; i += 128) {
                int r = i / 34, c = i % 34;
                int gy = gy0 + r, gx = gx0 + c;
                float v = 0.f;
                if (gy >= 0 && gy < H && gx >= 0 && gx < W) v = ip[(size_t)gy * W + gx];
                s_in[b][r][c] = v;
            }
        }
    };

    unsigned long long accA[16], accB[16];   // pairs (px,px+1) and (px+2,px+3)
    #pragma unroll
    for (int co = 0; co < 16; co++) { accA[co] = 0ull; accB[co] = 0ull; }

    load_tile(0, 0);
    __syncthreads();

    for (int ci = 0; ci < CI; ci++) {
        const int cur = ci & 1;
        if (ci + 1 < CI) load_tile(ci + 1, cur ^ 1);

        float iv[3][6];
        #pragma unroll
        for (int ky = 0; ky < 3; ky++)
            #pragma unroll
            for (int j = 0; j < 6; j++)
                iv[ky][j] = s_in[cur][py + ky][px + j];

        // 15 unique neighbor pairs; pairs j=0..2 feed accA (kx=j), j=2..4 feed accB
        unsigned long long pkv[3][5];
        #pragma unroll
        for (int ky = 0; ky < 3; ky++)
            #pragma unroll
            for (int j = 0; j < 5; j++)
                pkv[ky][j] = pk2(iv[ky][j], iv[ky][j + 1]);

        #pragma unroll
        for (int co = 0; co < 16; co++) {
            const unsigned long long* wp = &s_wd[(co * CI + ci) * 9];
            #pragma unroll
            for (int ky = 0; ky < 3; ky++)
                #pragma unroll
                for (int kx = 0; kx < 3; kx++) {
                    unsigned long long wq = wp[ky * 3 + kx];
                    accA[co] = fma2(pkv[ky][kx], wq, accA[co]);
                    accB[co] = fma2(pkv[ky][kx + 2], wq, accB[co]);
                }
        }
        __syncthreads();
    }

    // epilogue: optional store + per-channel stats accumulation
    const int y = ty * 16 + py;
    const bool yv = (y < H);
    #pragma unroll
    for (int co = 0; co < 16; co++) {
        int cg = cog * 16 + co;
        float b = bias[cg];
        size_t base = (((size_t)n * CO + cg) * H + y) * (size_t)W;
        float v[4];
        upk2(v[0], v[1], accA[co]);
        upk2(v[2], v[3], accB[co]);
        float s = 0.f, q = 0.f;
        #pragma unroll
        for (int p = 0; p < 4; p++) {
            int x = tx * 32 + px + p;
            float vv = v[p] + b;
            bool valid = yv && (x < W);
            if (STORE && valid) out[base + x] = vv;
            if (valid) { s += vv; q += vv * vv; }
        }
        #pragma unroll
        for (int o = 16; o > 0; o >>= 1) {
            s += __shfl_down_sync(0xffffffffu, s, o);
            q += __shfl_down_sync(0xffffffffu, q, o);
        }
        if (lane == 0) { redS[co][warp] = s; redQ[co][warp] = q; }
    }
    __syncthreads();
    if (tid < 16) {
        float S = redS[tid][0] + redS[tid][1] + redS[tid][2] + redS[tid][3];
        float Q = redQ[tid][0] + redQ[tid][1] + redQ[tid][2] + redQ[tid][3];
        int slot = (blockIdx.x + blockIdx.z * 977) & 511;
        int c = cog * 16 + tid;
        atomicAdd(&g_psum[(layer * 64 + c) * 512 + slot], S);
        atomicAdd(&g_psumsq[(layer * 64 + c) * 512 + slot], Q);
    }
}

// ---------------- layer1 fused: conv(1->16) + BN + ReLU + pool2 --------------
__launch_bounds__(128)
__global__ void conv1_pool_k(const float* __restrict__ in, const float* __restrict__ w,
                             const float* __restrict__ bias, float* __restrict__ out) {
    const int H = 224, W = 224;
    __shared__ float s_in[34][35];
    __shared__ float s_w[16 * 9];
    __shared__ float s_a[16], s_t[16];
    const int n = blockIdx.z;
    const int tx = blockIdx.x % 7, ty = blockIdx.x / 7;
    const int tid = threadIdx.x;

    for (int i = tid; i < 144; i += 128) s_w[i] = w[i];
    if (tid < 16) {
        float a = g_scale[tid];
        s_a[tid] = a;
        s_t[tid] = bias[tid] * a + g_shift[tid];
    }
    const int gx0 = tx * 32 - 1, gy0 = ty * 32 - 1;
    const float* ip = in + (size_t)n * H * W;
    for (int i = tid; i < 34 * 34; i += 128) {
        int r = i / 34, c = i % 34;
        int gy = gy0 + r, gx = gx0 + c;
        float v = 0.f;
        if (gy >= 0 && gy < H && gx >= 0 && gx < W) v = ip[(size_t)gy * W + gx];
        s_in[r][c] = v;
    }
    __syncthreads();

    const int pxp = (tid & 7) * 2;
    const int pyp = tid >> 3;
    const int cx = pxp * 2;
    const int cy = pyp * 2;

    float iv[4][6];
    #pragma unroll
    for (int r = 0; r < 4; r++)
        #pragma unroll
        for (int c = 0; c < 6; c++)
            iv[r][c] = s_in[cy + r][cx + c];

    // packed pairs: rows 0..3, pairs j=0..4
    unsigned long long pkv[4][5];
    #pragma unroll
    for (int r = 0; r < 4; r++)
        #pragma unroll
        for (int j = 0; j < 5; j++)
            pkv[r][j] = pk2(iv[r][j], iv[r][j + 1]);

    const int gxp = tx * 16 + pxp;
    const int gyp = ty * 16 + pyp;

    #pragma unroll
    for (int co = 0; co < 16; co++) {
        float a = s_a[co], t = s_t[co];
        // conv rows r=0,1 (two output rows), pixel pairs A=(0,1), B=(2,3)
        unsigned long long aA0 = 0ull, aB0 = 0ull, aA1 = 0ull, aB1 = 0ull;
        #pragma unroll
        for (int ky = 0; ky < 3; ky++)
            #pragma unroll
            for (int kx = 0; kx < 3; kx++) {
                float wv = s_w[co * 9 + ky * 3 + kx];
                unsigned long long wq = pk2(wv, wv);
                aA0 = fma2(pkv[ky + 0][kx], wq, aA0);
                aB0 = fma2(pkv[ky + 0][kx + 2], wq, aB0);
                aA1 = fma2(pkv[ky + 1][kx], wq, aA1);
                aB1 = fma2(pkv[ky + 1][kx + 2], wq, aB1);
            }
        float v00, v01, v02, v03, v10, v11, v12, v13;
        upk2(v00, v01, aA0); upk2(v02, v03, aB0);
        upk2(v10, v11, aA1); upk2(v12, v13, aB1);
        v00 = fmaf(v00, a, t); v01 = fmaf(v01, a, t); v02 = fmaf(v02, a, t); v03 = fmaf(v03, a, t);
        v10 = fmaf(v10, a, t); v11 = fmaf(v11, a, t); v12 = fmaf(v12, a, t); v13 = fmaf(v13, a, t);
        float p0 = fmaxf(fmaxf(v00, v01), fmaxf(v10, v11));
        float p1 = fmaxf(fmaxf(v02, v03), fmaxf(v12, v13));
        size_t base = (((size_t)n * 16 + co) * 112 + gyp) * (size_t)112 + gxp;
        out[base + 0] = fmaxf(p0, 0.f);
        out[base + 1] = fmaxf(p1, 0.f);
    }
}

// ---------------- BN affine + ReLU + 2x2 maxpool (layers 2,3) ----------------
__global__ void bn_relu_pool_k(const float* __restrict__ in, float* __restrict__ out,
                               int C, int H, int W, long long total) {
    long long idx = (long long)blockIdx.x * blockDim.x + threadIdx.x;
    if (idx >= total) return;
    int W2 = W >> 1, H2 = H >> 1;
    int x2 = (int)(idx % W2);
    long long r = idx / W2;
    int y2 = (int)(r % H2); r /= H2;
    int c  = (int)(r % C);
    int n  = (int)(r / C);
    const float2* p0 = (const float2*)(in + (((size_t)n * C + c) * H + 2 * y2) * (size_t)W) + x2;
    const float2* p1 = (const float2*)((const float*)p0 + W);
    float2 u = *p0, d = *p1;
    float a = g_scale[c], s = g_shift[c];
    float v0 = fmaf(u.x, a, s);
    float v1 = fmaf(u.y, a, s);
    float v2 = fmaf(d.x, a, s);
    float v3 = fmaf(d.y, a, s);
    float m = fmaxf(fmaxf(v0, v1), fmaxf(v2, v3));
    out[idx] = fmaxf(m, 0.f);
}

// ---------------- head: GAP + fc1 + LN + quantum circuit + fc2/fc3 -----------
__global__ void head_k(const float* __restrict__ pooled,   // (B,64,28,28)
                       const float* __restrict__ fc1_w, const float* __restrict__ fc1_b,
                       const float* __restrict__ ln_g,  const float* __restrict__ ln_b,
                       const float* __restrict__ qp,
                       const float* __restrict__ fc2_w, const float* __restrict__ fc2_b,
                       const float* __restrict__ fc3_w, const float* __restrict__ fc3_b,
                       float* __restrict__ out) {
    const int n = blockIdx.x;
    const int tid = threadIdx.x;
    const int warp = tid >> 5, lane = tid & 31;
    __shared__ float chm[64];
    __shared__ float qin[5];
    __shared__ float qres;

    const float* base = pooled + (size_t)n * 64 * 784;
    for (int j = 0; j < 8; j++) {
        int c = warp * 8 + j;
        const float* p = base + (size_t)c * 784;
        float s = 0.f;
        for (int i = lane; i < 784; i += 32) s += p[i];
        #pragma unroll
        for (int o = 16; o > 0; o >>= 1) s += __shfl_down_sync(0xffffffffu, s, o);
        if (lane == 0) chm[c] = s * (1.0f / 784.0f);
    }
    __syncthreads();

    if (tid == 0) {
        float h[5];
        #pragma unroll
        for (int o = 0; o < 5; o++) {
            float s = fc1_b[o];
            for (int i = 0; i < 64; i++) s += chm[i] * fc1_w[i * 5 + o];
            h[o] = s;
        }
        float mu = 0.f;
        #pragma unroll
        for (int o = 0; o < 5; o++) mu += h[o];
        mu *= 0.2f;
        float var = 0.f;
        #pragma unroll
        for (int o = 0; o < 5; o++) { float d = h[o] - mu; var += d * d; }
        var *= 0.2f;
        float r = rsqrtf(var + 1e-5f);
        #pragma unroll
        for (int o = 0; o < 5; o++) qin[o] = ln_g[o] * (h[o] - mu) * r + ln_b[o];
    }
    __syncthreads();

    // 5-qubit statevector: amplitude per lane (warp 0). wire i -> bit (1<<(4-i))
    if (warp == 0) {
        float are = (lane == 0) ? 1.f : 0.f, aim = 0.f;
        const unsigned fm = 0xffffffffu;
        for (int l = 0; l < 3; l++) {
            #pragma unroll
            for (int i = 0; i < 5; i++) {
                int m = 1 << (4 - i);
                float sn, cs; sincosf(qin[i] * 0.5f, &sn, &cs);
                float pre = __shfl_xor_sync(fm, are, m);
                float pim = __shfl_xor_sync(fm, aim, m);
                float nre = cs * are + sn * pim;
                float nim = cs * aim - sn * pre;
                are = nre; aim = nim;
            }
            #pragma unroll
            for (int i = 0; i < 5; i++) {
                int m = 1 << (4 - i);
                float sy, cy; sincosf(qp[l * 10 + i] * 0.5f, &sy, &cy);
                float pre = __shfl_xor_sync(fm, are, m);
                float pim = __shfl_xor_sync(fm, aim, m);
                float sgn = (lane & m) ? sy : -sy;
                float nre = cy * are + sgn * pre;
                float nim = cy * aim + sgn * pim;
                float sz, cz; sincosf(qp[l * 10 + i + 5] * 0.5f, &sz, &cz);
                float zg = (lane & m) ? -sz : sz;
                are = nre * cz + zg * nim;
                aim = nim * cz - zg * nre;
            }
            const int cw[5] = {0, 1, 2, 3, 4};
            const int tw[5] = {1, 2, 3, 4, 0};
            #pragma unroll
            for (int k = 0; k < 5; k++) {
                int mc = 1 << (4 - cw[k]);
                int mt = 1 << (4 - tw[k]);
                int src = (lane & mc) ? (lane ^ mt) : lane;
                are = __shfl_sync(fm, are, src);
                aim = __shfl_sync(fm, aim, src);
            }
        }
        float p = are * are + aim * aim;
        float sgn = (__popc(lane & 28) & 1) ? -1.f : 1.f;
        float v = p * sgn;
        #pragma unroll
        for (int o = 16; o > 0; o >>= 1) v += __shfl_down_sync(fm, v, o);
        if (lane == 0) qres = v;
    }
    __syncthreads();

    if (tid == 0) {
        float q = qres;
        float l0 = fc3_b[0], l1 = fc3_b[1];
        for (int j = 0; j < 32; j++) {
            float h2 = fmaxf(q * fc2_w[j] + fc2_b[j], 0.f);
            l0 += h2 * fc3_w[j * 2 + 0];
            l1 += h2 * fc3_w[j * 2 + 1];
        }
        float mx = fmaxf(l0, l1);
        float lse = mx + logf(expf(l0 - mx) + expf(l1 - mx));
        out[n * 2 + 0] = l0 - lse;
        out[n * 2 + 1] = l1 - lse;
    }
}

// ---------------- host launcher ----------------------------------------------
extern "C" void kernel_launch(void* const* d_in, const int* in_sizes, int n_in,
                              void* d_out, int out_size) {
    const float* x    = (const float*)d_in[0];
    const float* c1w  = (const float*)d_in[1];
    const float* c1b  = (const float*)d_in[2];
    const float* bn1g = (const float*)d_in[3];
    const float* bn1b = (const float*)d_in[4];
    const float* c2w  = (const float*)d_in[5];
    const float* c2b  = (const float*)d_in[6];
    const float* bn2g = (const float*)d_in[7];
    const float* bn2b = (const float*)d_in[8];
    const float* c3w  = (const float*)d_in[9];
    const float* c3b  = (const float*)d_in[10];
    const float* bn3g = (const float*)d_in[11];
    const float* bn3b = (const float*)d_in[12];
    const float* fc1w = (const float*)d_in[13];
    const float* fc1b = (const float*)d_in[14];
    const float* lng  = (const float*)d_in[15];
    const float* lnb  = (const float*)d_in[16];
    const float* qp   = (const float*)d_in[17];
    const float* fc2w = (const float*)d_in[18];
    const float* fc2b = (const float*)d_in[19];
    const float* fc3w = (const float*)d_in[20];
    const float* fc3b = (const float*)d_in[21];
    float* out = (float*)d_out;

    float *conv, *poolA, *poolB;
    cudaGetSymbolAddress((void**)&conv,  g_conv);
    cudaGetSymbolAddress((void**)&poolA, g_poolA);
    cudaGetSymbolAddress((void**)&poolB, g_poolB);

    const int B = 256;

    zero_partials_k<<<(3 * 64 * 512 + 511) / 512, 512>>>();

    // ---- Layer 1: conv(1->16) @224, stats pass (no store) + fused pool pass ----
    {
        int H = 224, W = 224, CO = 16;
        int txs = (W + 31) / 32, tys = (H + 15) / 16;
        conv3x3_k<1, false><<<dim3(txs * tys, 1, B), 128>>>(x, c1w, c1b, nullptr, CO, H, W, txs, 0);
        finalize_k<<<1, 64>>>(bn1g, bn1b, CO, 0, 1.0 / ((double)B * H * W));
        conv1_pool_k<<<dim3(49, 1, B), 128>>>(x, c1w, c1b, poolA);
    }
    // ---- Layer 2: conv(16->32) @112 with fused stats ----
    {
        int H = 112, W = 112, CO = 32;
        int txs = (W + 31) / 32, tys = (H + 15) / 16;
        conv3x3_k<16, true><<<dim3(txs * tys, CO / 16, B), 128>>>(poolA, c2w, c2b, conv, CO, H, W, txs, 1);
        finalize_k<<<1, 64>>>(bn2g, bn2b, CO, 1, 1.0 / ((double)B * H * W));
        long long tot = (long long)B * CO * (H / 2) * (W / 2);
        bn_relu_pool_k<<<(unsigned)((tot + 255) / 256), 256>>>(conv, poolB, CO, H, W, tot);
    }
    // ---- Layer 3: conv(32->64) @56 with fused stats ----
    {
        int H = 56, W = 56, CO = 64;
        int txs = (W + 31) / 32, tys = (H + 15) / 16;
        conv3x3_k<32, true><<<dim3(txs * tys, CO / 16, B), 128>>>(poolB, c3w, c3b, conv, CO, H, W, txs, 2);
        finalize_k<<<1, 64>>>(bn3g, bn3b, CO, 2, 1.0 / ((double)B * H * W));
        long long tot = (long long)B * CO * (H / 2) * (W / 2);
        bn_relu_pool_k<<<(unsigned)((tot + 255) / 256), 256>>>(conv, poolA, CO, H, W, tot);
    }
    // ---- Head ----
    head_k<<<B, 256>>>(poolA, fc1w, fc1b, lng, lnb, qp, fc2w, fc2b, fc3w, fc3b, out);
}

// round 6
// speedup vs baseline: 1.0748x; 1.0748x over previous
#include <cuda_runtime.h>
#include <math.h>
#include <stdint.h>

// ---------------- scratch (static device memory; no allocs allowed) ----------
__device__ float g_conv[102760448];   // max stored conv out: 256*32*112*112 (411 MB)
__device__ float g_poolA[51380224];   // 256*16*112*112 (205 MB); also pool3 out (51 MB)
__device__ float g_poolB[25690112];   // 256*32*56*56  (103 MB)
__device__ float g_psum[3 * 64 * 512];
__device__ float g_psumsq[3 * 64 * 512];
__device__ float g_scale[64];
__device__ float g_shift[64];

// ---------------- zero partial-stat buffers ----------------------------------
__global__ void zero_partials_k() {
    int i = blockIdx.x * blockDim.x + threadIdx.x;
    if (i < 3 * 64 * 512) { g_psum[i] = 0.f; g_psumsq[i] = 0.f; }
}

// ---------------- finalize: reduce partials -> scale/shift --------------------
__global__ void finalize_k(const float* __restrict__ gam, const float* __restrict__ bet,
                           int C, int layer, double inv_cnt) {
    int c = threadIdx.x;
    if (c < C) {
        const float* ps = &g_psum[(layer * 64 + c) * 512];
        const float* pq = &g_psumsq[(layer * 64 + c) * 512];
        double S = 0.0, Q = 0.0;
        for (int i = 0; i < 512; i++) { S += (double)ps[i]; Q += (double)pq[i]; }
        double mean = S * inv_cnt;
        double var = Q * inv_cnt - mean * mean;
        float sc = gam[c] * rsqrtf((float)var + 1e-5f);
        g_scale[c] = sc;
        g_shift[c] = bet[c] - sc * (float)mean;
    }
}

// ---------------- direct 3x3 conv, vectorized LDS, fused BN stats ------------
// Block = 128 threads. Tile = 32(x) x 16(y); each thread: 4 px x 16 co.
// Weights padded to 12 floats (2xLDS.128+LDS.32); input pitch 36 (float4 loads).
// Double-buffered input tile: one __syncthreads per ci.
template<int CI, bool STORE>
__launch_bounds__(128)
__global__ void conv3x3_k(const float* __restrict__ in, const float* __restrict__ w,
                          const float* __restrict__ bias, float* __restrict__ out,
                          int CO, int H, int W, int tiles_x, int layer) {
    __shared__ __align__(16) float s_in[2][18][36];
    __shared__ __align__(16) float s_w[CI * 16 * 12];   // 9 taps padded to 12
    __shared__ float redS[16][4], redQ[16][4];
    const int n   = blockIdx.z;
    const int cog = blockIdx.y;            // group of 16 output channels
    const int tile = blockIdx.x;
    const int tx = tile % tiles_x, ty = tile / tiles_x;
    const int tid = threadIdx.x;
    const int warp = tid >> 5, lane = tid & 31;

    for (int i = tid; i < CI * 16 * 9; i += 128) {
        int g = i / 9, t = i - g * 9;
        s_w[g * 12 + t] = w[(size_t)(cog * 16) * CI * 9 + i];
    }

    const int px = (tid & 7) * 4;
    const int py = tid >> 3;
    const int gx0 = tx * 32 - 1;
    const int gy0 = ty * 16 - 1;
    const bool interior = (gx0 >= 0) && (gy0 >= 0) && (gx0 + 33 < W) && (gy0 + 17 < H);

    auto load_tile = [&](int ci, int b) {
        const float* ip = in + ((size_t)n * CI + ci) * (size_t)H * W;
        if (interior) {
            for (int i = tid; i < 18 * 34; i += 128) {
                int r = i / 34, c = i - r * 34;
                s_in[b][r][c] = ip[(size_t)(gy0 + r) * W + (gx0 + c)];
            }
        } else {
            for (int i = tid; i < 18 * 34; i += 128) {
                int r = i / 34, c = i - r * 34;
                int gy = gy0 + r, gx = gx0 + c;
                float v = 0.f;
                if (gy >= 0 && gy < H && gx >= 0 && gx < W) v = ip[(size_t)gy * W + gx];
                s_in[b][r][c] = v;
            }
        }
    };

    float acc[16][4];
    #pragma unroll
    for (int co = 0; co < 16; co++)
        #pragma unroll
        for (int p = 0; p < 4; p++) acc[co][p] = 0.f;

    load_tile(0, 0);
    __syncthreads();

    for (int ci = 0; ci < CI; ci++) {
        const int cur = ci & 1;
        if (ci + 1 < CI) load_tile(ci + 1, cur ^ 1);

        float iv[3][6];
        #pragma unroll
        for (int ky = 0; ky < 3; ky++) {
            float4 a0 = *(const float4*)&s_in[cur][py + ky][px];
            float2 b0 = *(const float2*)&s_in[cur][py + ky][px + 4];
            iv[ky][0] = a0.x; iv[ky][1] = a0.y; iv[ky][2] = a0.z;
            iv[ky][3] = a0.w; iv[ky][4] = b0.x; iv[ky][5] = b0.y;
        }

        #pragma unroll
        for (int co = 0; co < 16; co++) {
            const float* wp = &s_w[(co * CI + ci) * 12];
            float4 wA = *(const float4*)wp;        // taps 0..3
            float4 wB = *(const float4*)(wp + 4);  // taps 4..7
            float  w8 = wp[8];
            float wv[9] = {wA.x, wA.y, wA.z, wA.w, wB.x, wB.y, wB.z, wB.w, w8};
            #pragma unroll
            for (int ky = 0; ky < 3; ky++)
                #pragma unroll
                for (int kx = 0; kx < 3; kx++) {
                    float wq = wv[ky * 3 + kx];
                    #pragma unroll
                    for (int p = 0; p < 4; p++)
                        acc[co][p] = fmaf(iv[ky][kx + p], wq, acc[co][p]);
                }
        }
        __syncthreads();
    }

    // epilogue: optional store + per-channel stats accumulation
    const int y = ty * 16 + py;
    const bool yv = (y < H);
    #pragma unroll
    for (int co = 0; co < 16; co++) {
        int cg = cog * 16 + co;
        float b = bias[cg];
        size_t base = (((size_t)n * CO + cg) * H + y) * (size_t)W;
        float s = 0.f, q = 0.f;
        #pragma unroll
        for (int p = 0; p < 4; p++) {
            int x = tx * 32 + px + p;
            float v = acc[co][p] + b;
            bool valid = yv && (x < W);
            if (STORE && valid) out[base + x] = v;
            if (valid) { s += v; q += v * v; }
        }
        #pragma unroll
        for (int o = 16; o > 0; o >>= 1) {
            s += __shfl_down_sync(0xffffffffu, s, o);
            q += __shfl_down_sync(0xffffffffu, q, o);
        }
        if (lane == 0) { redS[co][warp] = s; redQ[co][warp] = q; }
    }
    __syncthreads();
    if (tid < 16) {
        float S = redS[tid][0] + redS[tid][1] + redS[tid][2] + redS[tid][3];
        float Q = redQ[tid][0] + redQ[tid][1] + redQ[tid][2] + redQ[tid][3];
        int slot = (blockIdx.x + blockIdx.z * 977) & 511;
        int c = cog * 16 + tid;
        atomicAdd(&g_psum[(layer * 64 + c) * 512 + slot], S);
        atomicAdd(&g_psumsq[(layer * 64 + c) * 512 + slot], Q);
    }
}

// ---------------- layer1 fused: conv(1->16) + BN + ReLU + pool2 --------------
__launch_bounds__(128)
__global__ void conv1_pool_k(const float* __restrict__ in, const float* __restrict__ w,
                             const float* __restrict__ bias, float* __restrict__ out) {
    const int H = 224, W = 224;
    __shared__ float s_in[34][35];
    __shared__ float s_w[16 * 9];
    __shared__ float s_a[16], s_t[16];
    const int n = blockIdx.z;
    const int tx = blockIdx.x % 7, ty = blockIdx.x / 7;
    const int tid = threadIdx.x;

    for (int i = tid; i < 144; i += 128) s_w[i] = w[i];
    if (tid < 16) {
        float a = g_scale[tid];
        s_a[tid] = a;
        s_t[tid] = bias[tid] * a + g_shift[tid];
    }
    const int gx0 = tx * 32 - 1, gy0 = ty * 32 - 1;
    const float* ip = in + (size_t)n * H * W;
    for (int i = tid; i < 34 * 34; i += 128) {
        int r = i / 34, c = i % 34;
        int gy = gy0 + r, gx = gx0 + c;
        float v = 0.f;
        if (gy >= 0 && gy < H && gx >= 0 && gx < W) v = ip[(size_t)gy * W + gx];
        s_in[r][c] = v;
    }
    __syncthreads();

    const int pxp = (tid & 7) * 2;
    const int pyp = tid >> 3;
    const int cx = pxp * 2;
    const int cy = pyp * 2;

    float iv[4][6];
    #pragma unroll
    for (int r = 0; r < 4; r++)
        #pragma unroll
        for (int c = 0; c < 6; c++)
            iv[r][c] = s_in[cy + r][cx + c];

    const int gxp = tx * 16 + pxp;
    const int gyp = ty * 16 + pyp;

    #pragma unroll
    for (int co = 0; co < 16; co++) {
        float w0 = s_w[co * 9 + 0], w1 = s_w[co * 9 + 1], w2 = s_w[co * 9 + 2];
        float w3 = s_w[co * 9 + 3], w4 = s_w[co * 9 + 4], w5 = s_w[co * 9 + 5];
        float w6 = s_w[co * 9 + 6], w7 = s_w[co * 9 + 7], w8 = s_w[co * 9 + 8];
        float a = s_a[co], t = s_t[co];
        float v[2][4];
        #pragma unroll
        for (int r = 0; r < 2; r++)
            #pragma unroll
            for (int c = 0; c < 4; c++) {
                float s = iv[r + 0][c + 0] * w0 + iv[r + 0][c + 1] * w1 + iv[r + 0][c + 2] * w2
                        + iv[r + 1][c + 0] * w3 + iv[r + 1][c + 1] * w4 + iv[r + 1][c + 2] * w5
                        + iv[r + 2][c + 0] * w6 + iv[r + 2][c + 1] * w7 + iv[r + 2][c + 2] * w8;
                v[r][c] = fmaf(s, a, t);
            }
        float p0 = fmaxf(fmaxf(v[0][0], v[0][1]), fmaxf(v[1][0], v[1][1]));
        float p1 = fmaxf(fmaxf(v[0][2], v[0][3]), fmaxf(v[1][2], v[1][3]));
        size_t base = (((size_t)n * 16 + co) * 112 + gyp) * (size_t)112 + gxp;
        out[base + 0] = fmaxf(p0, 0.f);
        out[base + 1] = fmaxf(p1, 0.f);
    }
}

// ---------------- BN affine + ReLU + 2x2 maxpool (layers 2,3) ----------------
__global__ void bn_relu_pool_k(const float* __restrict__ in, float* __restrict__ out,
                               int C, int H, int W, long long total) {
    long long idx = (long long)blockIdx.x * blockDim.x + threadIdx.x;
    if (idx >= total) return;
    int W2 = W >> 1, H2 = H >> 1;
    int x2 = (int)(idx % W2);
    long long r = idx / W2;
    int y2 = (int)(r % H2); r /= H2;
    int c  = (int)(r % C);
    int n  = (int)(r / C);
    const float2* p0 = (const float2*)(in + (((size_t)n * C + c) * H + 2 * y2) * (size_t)W) + x2;
    const float2* p1 = (const float2*)((const float*)p0 + W);
    float2 u = *p0, d = *p1;
    float a = g_scale[c], s = g_shift[c];
    float v0 = fmaf(u.x, a, s);
    float v1 = fmaf(u.y, a, s);
    float v2 = fmaf(d.x, a, s);
    float v3 = fmaf(d.y, a, s);
    float m = fmaxf(fmaxf(v0, v1), fmaxf(v2, v3));
    out[idx] = fmaxf(m, 0.f);
}

// ---------------- head: GAP + fc1 + LN + quantum circuit + fc2/fc3 -----------
__global__ void head_k(const float* __restrict__ pooled,   // (B,64,28,28)
                       const float* __restrict__ fc1_w, const float* __restrict__ fc1_b,
                       const float* __restrict__ ln_g,  const float* __restrict__ ln_b,
                       const float* __restrict__ qp,
                       const float* __restrict__ fc2_w, const float* __restrict__ fc2_b,
                       const float* __restrict__ fc3_w, const float* __restrict__ fc3_b,
                       float* __restrict__ out) {
    const int n = blockIdx.x;
    const int tid = threadIdx.x;
    const int warp = tid >> 5, lane = tid & 31;
    __shared__ float chm[64];
    __shared__ float qin[5];
    __shared__ float qres;

    const float* base = pooled + (size_t)n * 64 * 784;
    for (int j = 0; j < 8; j++) {
        int c = warp * 8 + j;
        const float* p = base + (size_t)c * 784;
        float s = 0.f;
        for (int i = lane; i < 784; i += 32) s += p[i];
        #pragma unroll
        for (int o = 16; o > 0; o >>= 1) s += __shfl_down_sync(0xffffffffu, s, o);
        if (lane == 0) chm[c] = s * (1.0f / 784.0f);
    }
    __syncthreads();

    if (tid == 0) {
        float h[5];
        #pragma unroll
        for (int o = 0; o < 5; o++) {
            float s = fc1_b[o];
            for (int i = 0; i < 64; i++) s += chm[i] * fc1_w[i * 5 + o];
            h[o] = s;
        }
        float mu = 0.f;
        #pragma unroll
        for (int o = 0; o < 5; o++) mu += h[o];
        mu *= 0.2f;
        float var = 0.f;
        #pragma unroll
        for (int o = 0; o < 5; o++) { float d = h[o] - mu; var += d * d; }
        var *= 0.2f;
        float r = rsqrtf(var + 1e-5f);
        #pragma unroll
        for (int o = 0; o < 5; o++) qin[o] = ln_g[o] * (h[o] - mu) * r + ln_b[o];
    }
    __syncthreads();

    // 5-qubit statevector: amplitude per lane (warp 0). wire i -> bit (1<<(4-i))
    if (warp == 0) {
        float are = (lane == 0) ? 1.f : 0.f, aim = 0.f;
        const unsigned fm = 0xffffffffu;
        for (int l = 0; l < 3; l++) {
            #pragma unroll
            for (int i = 0; i < 5; i++) {
                int m = 1 << (4 - i);
                float sn, cs; sincosf(qin[i] * 0.5f, &sn, &cs);
                float pre = __shfl_xor_sync(fm, are, m);
                float pim = __shfl_xor_sync(fm, aim, m);
                float nre = cs * are + sn * pim;
                float nim = cs * aim - sn * pre;
                are = nre; aim = nim;
            }
            #pragma unroll
            for (int i = 0; i < 5; i++) {
                int m = 1 << (4 - i);
                float sy, cy; sincosf(qp[l * 10 + i] * 0.5f, &sy, &cy);
                float pre = __shfl_xor_sync(fm, are, m);
                float pim = __shfl_xor_sync(fm, aim, m);
                float sgn = (lane & m) ? sy : -sy;
                float nre = cy * are + sgn * pre;
                float nim = cy * aim + sgn * pim;
                float sz, cz; sincosf(qp[l * 10 + i + 5] * 0.5f, &sz, &cz);
                float zg = (lane & m) ? -sz : sz;
                are = nre * cz + zg * nim;
                aim = nim * cz - zg * nre;
            }
            const int cw[5] = {0, 1, 2, 3, 4};
            const int tw[5] = {1, 2, 3, 4, 0};
            #pragma unroll
            for (int k = 0; k < 5; k++) {
                int mc = 1 << (4 - cw[k]);
                int mt = 1 << (4 - tw[k]);
                int src = (lane & mc) ? (lane ^ mt) : lane;
                are = __shfl_sync(fm, are, src);
                aim = __shfl_sync(fm, aim, src);
            }
        }
        float p = are * are + aim * aim;
        float sgn = (__popc(lane & 28) & 1) ? -1.f : 1.f;
        float v = p * sgn;
        #pragma unroll
        for (int o = 16; o > 0; o >>= 1) v += __shfl_down_sync(fm, v, o);
        if (lane == 0) qres = v;
    }
    __syncthreads();

    if (tid == 0) {
        float q = qres;
        float l0 = fc3_b[0], l1 = fc3_b[1];
        for (int j = 0; j < 32; j++) {
            float h2 = fmaxf(q * fc2_w[j] + fc2_b[j], 0.f);
            l0 += h2 * fc3_w[j * 2 + 0];
            l1 += h2 * fc3_w[j * 2 + 1];
        }
        float mx = fmaxf(l0, l1);
        float lse = mx + logf(expf(l0 - mx) + expf(l1 - mx));
        out[n * 2 + 0] = l0 - lse;
        out[n * 2 + 1] = l1 - lse;
    }
}

// ---------------- host launcher ----------------------------------------------
extern "C" void kernel_launch(void* const* d_in, const int* in_sizes, int n_in,
                              void* d_out, int out_size) {
    const float* x    = (const float*)d_in[0];
    const float* c1w  = (const float*)d_in[1];
    const float* c1b  = (const float*)d_in[2];
    const float* bn1g = (const float*)d_in[3];
    const float* bn1b = (const float*)d_in[4];
    const float* c2w  = (const float*)d_in[5];
    const float* c2b  = (const float*)d_in[6];
    const float* bn2g = (const float*)d_in[7];
    const float* bn2b = (const float*)d_in[8];
    const float* c3w  = (const float*)d_in[9];
    const float* c3b  = (const float*)d_in[10];
    const float* bn3g = (const float*)d_in[11];
    const float* bn3b = (const float*)d_in[12];
    const float* fc1w = (const float*)d_in[13];
    const float* fc1b = (const float*)d_in[14];
    const float* lng  = (const float*)d_in[15];
    const float* lnb  = (const float*)d_in[16];
    const float* qp   = (const float*)d_in[17];
    const float* fc2w = (const float*)d_in[18];
    const float* fc2b = (const float*)d_in[19];
    const float* fc3w = (const float*)d_in[20];
    const float* fc3b = (const float*)d_in[21];
    float* out = (float*)d_out;

    float *conv, *poolA, *poolB;
    cudaGetSymbolAddress((void**)&conv,  g_conv);
    cudaGetSymbolAddress((void**)&poolA, g_poolA);
    cudaGetSymbolAddress((void**)&poolB, g_poolB);

    const int B = 256;

    zero_partials_k<<<(3 * 64 * 512 + 511) / 512, 512>>>();

    // ---- Layer 1: conv(1->16) @224, stats pass (no store) + fused pool pass ----
    {
        int H = 224, W = 224, CO = 16;
        int txs = (W + 31) / 32, tys = (H + 15) / 16;
        conv3x3_k<1, false><<<dim3(txs * tys, 1, B), 128>>>(x, c1w, c1b, nullptr, CO, H, W, txs, 0);
        finalize_k<<<1, 64>>>(bn1g, bn1b, CO, 0, 1.0 / ((double)B * H * W));
        conv1_pool_k<<<dim3(49, 1, B), 128>>>(x, c1w, c1b, poolA);
    }
    // ---- Layer 2: conv(16->32) @112 with fused stats ----
    {
        int H = 112, W = 112, CO = 32;
        int txs = (W + 31) / 32, tys = (H + 15) / 16;
        conv3x3_k<16, true><<<dim3(txs * tys, CO / 16, B), 128>>>(poolA, c2w, c2b, conv, CO, H, W, txs, 1);
        finalize_k<<<1, 64>>>(bn2g, bn2b, CO, 1, 1.0 / ((double)B * H * W));
        long long tot = (long long)B * CO * (H / 2) * (W / 2);
        bn_relu_pool_k<<<(unsigned)((tot + 255) / 256), 256>>>(conv, poolB, CO, H, W, tot);
    }
    // ---- Layer 3: conv(32->64) @56 with fused stats ----
    {
        int H = 56, W = 56, CO = 64;
        int txs = (W + 31) / 32, tys = (H + 15) / 16;
        conv3x3_k<32, true><<<dim3(txs * tys, CO / 16, B), 128>>>(poolB, c3w, c3b, conv, CO, H, W, txs, 2);
        finalize_k<<<1, 64>>>(bn3g, bn3b, CO, 2, 1.0 / ((double)B * H * W));
        long long tot = (long long)B * CO * (H / 2) * (W / 2);
        bn_relu_pool_k<<<(unsigned)((tot + 255) / 256), 256>>>(conv, poolA, CO, H, W, tot);
    }
    // ---- Head ----
    head_k<<<B, 256>>>(poolA, fc1w, fc1b, lng, lnb, qp, fc2w, fc2b, fc3w, fc3b, out);
}

// round 7
// speedup vs baseline: 2.2627x; 2.1053x over previous
#include <cuda_runtime.h>
#include <math.h>
#include <stdint.h>

// ---------------- scratch (static device memory; no allocs allowed) ----------
__device__ float g_conv[102760448];   // max stored conv out: 256*32*112*112 (411 MB)
__device__ float g_poolA[51380224];   // 256*16*112*112 (205 MB); also pool3 out (51 MB)
__device__ float g_poolB[25690112];   // 256*32*56*56  (103 MB)
__device__ float g_psum[3 * 64 * 512];
__device__ float g_psumsq[3 * 64 * 512];
__device__ float g_scale[64];
__device__ float g_shift[64];
__device__ uint32_t g_wT2[9 * 16 * 32];   // tf32 weights [tap][ci][co]
__device__ uint32_t g_wT3[9 * 32 * 64];

__device__ __forceinline__ uint32_t f2tf32(float v) {
    uint32_t t; asm("cvt.rna.tf32.f32 %0, %1;" : "=r"(t) : "f"(v));
    return t;
}

// ---------------- zero partial-stat buffers ----------------------------------
__global__ void zero_partials_k() {
    int i = blockIdx.x * blockDim.x + threadIdx.x;
    if (i < 3 * 64 * 512) { g_psum[i] = 0.f; g_psumsq[i] = 0.f; }
}

// ---------------- weight transpose + tf32 round prep --------------------------
__global__ void wprep_k(const float* __restrict__ w2, const float* __restrict__ w3) {
    int i = blockIdx.x * 256 + threadIdx.x;
    if (i < 9 * 16 * 32) {
        int co = i / 144, rem = i - co * 144, ci = rem / 9, tap = rem - ci * 9;
        g_wT2[(tap * 16 + ci) * 32 + co] = f2tf32(w2[i]);
    }
    if (i < 9 * 32 * 64) {
        int co = i / 288, rem = i - co * 288, ci = rem / 9, tap = rem - ci * 9;
        g_wT3[(tap * 32 + ci) * 64 + co] = f2tf32(w3[i]);
    }
}

// ---------------- finalize: reduce partials -> scale/shift --------------------
__global__ void finalize_k(const float* __restrict__ gam, const float* __restrict__ bet,
                           int C, int layer, double inv_cnt) {
    int c = threadIdx.x;
    if (c < C) {
        const float* ps = &g_psum[(layer * 64 + c) * 512];
        const float* pq = &g_psumsq[(layer * 64 + c) * 512];
        double S = 0.0, Q = 0.0;
        for (int i = 0; i < 512; i++) { S += (double)ps[i]; Q += (double)pq[i]; }
        double mean = S * inv_cnt;
        double var = Q * inv_cnt - mean * mean;
        float sc = gam[c] * rsqrtf((float)var + 1e-5f);
        g_scale[c] = sc;
        g_shift[c] = bet[c] - sc * (float)mean;
    }
}

// ---------------- TF32 tensor-core shift-GEMM 3x3 conv + fused BN stats ------
// Block 256 thr (8 warps). Spatial tile 16x16. mma.m16n8k8: M=16 px of one row,
// N=8 output channels, K=8 input channels; 9 taps = 9 shifted GEMMs.
template<int CI, int CO>
__launch_bounds__(256)
__global__ void conv_mma_k(const float* __restrict__ in, const uint32_t* __restrict__ wT,
                           const float* __restrict__ bias, float* __restrict__ out,
                           int H, int W, int tiles_x, int layer) {
    constexpr int CIP = (CI == 32) ? 36 : 20;   // bank-conflict-free pitch
    constexpr int KS  = CI / 8;
    constexpr int NT  = CO / 8;                 // n-tiles
    constexpr int MSEG = 8 / NT;                // warps per ntile (m split)
    constexpr int MT_PER = 16 / MSEG;
    __shared__ uint32_t s_in[18][18][CIP];

    const int n = blockIdx.z;
    const int tile = blockIdx.x;
    const int tx0 = (tile % tiles_x) * 16;
    const int ty0 = (tile / tiles_x) * 16;
    const int tid = threadIdx.x, warp = tid >> 5, lane = tid & 31;

    // ---- load 18x18xCI halo tile (channel-last, tf32-rounded) ----
    const int gx0 = tx0 - 1, gy0 = ty0 - 1;
    for (int i = tid; i < CI * 324; i += 256) {
        int ci = i / 324, rem = i - ci * 324;
        int r = rem / 18, c = rem - r * 18;
        int gy = gy0 + r, gx = gx0 + c;
        float v = 0.f;
        if (gy >= 0 && gy < H && gx >= 0 && gx < W)
            v = in[((size_t)n * CI + ci) * (size_t)(H * W) + (size_t)gy * W + gx];
        s_in[r][c][ci] = f2tf32(v);
    }

    const int ntile = warp % NT;
    const int mseg  = warp / NT;
    const int ci_lo = lane & 3;
    const int xA    = lane >> 2;

    // ---- preload B fragments into registers ----
    uint32_t breg[9][KS][2];
    #pragma unroll
    for (int tap = 0; tap < 9; tap++)
        #pragma unroll
        for (int ks = 0; ks < KS; ks++) {
            breg[tap][ks][0] = wT[(tap * CI + ks * 8 + ci_lo) * CO + ntile * 8 + xA];
            breg[tap][ks][1] = wT[(tap * CI + ks * 8 + ci_lo + 4) * CO + ntile * 8 + xA];
        }
    const int co_e = ntile * 8 + 2 * ci_lo;     // this lane's channel pair
    const float b_lo = bias[co_e], b_hi = bias[co_e + 1];

    __syncthreads();

    float sA = 0.f, qA = 0.f, sB = 0.f, qB = 0.f;
    const size_t chan_stride = (size_t)H * W;

    for (int mi = 0; mi < MT_PER; mi++) {
        int mt = mseg * MT_PER + mi;            // row within tile
        int y = ty0 + mt;
        if (y >= H) break;
        float c0 = 0.f, c1 = 0.f, c2 = 0.f, c3 = 0.f;
        #pragma unroll
        for (int tap = 0; tap < 9; tap++) {
            const int ky = tap / 3, kx = tap - ky * 3;
            #pragma unroll
            for (int ks = 0; ks < KS; ks++) {
                uint32_t a0 = s_in[mt + ky][xA + kx][ks * 8 + ci_lo];
                uint32_t a1 = s_in[mt + ky][xA + 8 + kx][ks * 8 + ci_lo];
                uint32_t a2 = s_in[mt + ky][xA + kx][ks * 8 + ci_lo + 4];
                uint32_t a3 = s_in[mt + ky][xA + 8 + kx][ks * 8 + ci_lo + 4];
                asm volatile(
                    "mma.sync.aligned.m16n8k8.row.col.f32.tf32.tf32.f32 "
                    "{%0,%1,%2,%3}, {%4,%5,%6,%7}, {%8,%9}, {%0,%1,%2,%3};"
                    : "+f"(c0), "+f"(c1), "+f"(c2), "+f"(c3)
                    : "r"(a0), "r"(a1), "r"(a2), "r"(a3),
                      "r"(breg[tap][ks][0]), "r"(breg[tap][ks][1]));
            }
        }
        // epilogue: bias + masked store + stats
        int x_lo = tx0 + xA, x_hi = x_lo + 8;
        size_t base = (((size_t)n * CO + co_e) * H + y) * (size_t)W;
        float v00 = c0 + b_lo, v01 = c1 + b_hi, v10 = c2 + b_lo, v11 = c3 + b_hi;
        if (x_lo < W) {
            out[base + x_lo] = v00;
            out[base + chan_stride + x_lo] = v01;
            sA += v00; qA += v00 * v00; sB += v01; qB += v01 * v01;
        }
        if (x_hi < W) {
            out[base + x_hi] = v10;
            out[base + chan_stride + x_hi] = v11;
            sA += v10; qA += v10 * v10; sB += v11; qB += v11 * v11;
        }
    }

    // reduce stats across the 8 lanes sharing (lane&3), then atomically scatter
    #pragma unroll
    for (int off = 4; off < 32; off <<= 1) {
        sA += __shfl_xor_sync(0xffffffffu, sA, off);
        qA += __shfl_xor_sync(0xffffffffu, qA, off);
        sB += __shfl_xor_sync(0xffffffffu, sB, off);
        qB += __shfl_xor_sync(0xffffffffu, qB, off);
    }
    if (lane < 4) {
        int slot = (blockIdx.x + blockIdx.z * 977 + warp * 53) & 511;
        atomicAdd(&g_psum  [(layer * 64 + co_e) * 512 + slot], sA);
        atomicAdd(&g_psumsq[(layer * 64 + co_e) * 512 + slot], qA);
        atomicAdd(&g_psum  [(layer * 64 + co_e + 1) * 512 + slot], sB);
        atomicAdd(&g_psumsq[(layer * 64 + co_e + 1) * 512 + slot], qB);
    }
}

// ---------------- layer1 stats: scalar direct conv (CI=1), no store ----------
template<int CI, bool STORE>
__launch_bounds__(128)
__global__ void conv3x3_k(const float* __restrict__ in, const float* __restrict__ w,
                          const float* __restrict__ bias, float* __restrict__ out,
                          int CO, int H, int W, int tiles_x, int layer) {
    __shared__ float s_in[2][18][36];
    __shared__ float s_w[CI * 16 * 9];
    __shared__ float redS[16][4], redQ[16][4];
    const int n   = blockIdx.z;
    const int cog = blockIdx.y;
    const int tile = blockIdx.x;
    const int tx = tile % tiles_x, ty = tile / tiles_x;
    const int tid = threadIdx.x;
    const int warp = tid >> 5, lane = tid & 31;

    for (int i = tid; i < CI * 16 * 9; i += 128)
        s_w[i] = w[(size_t)(cog * 16) * CI * 9 + i];

    const int px = (tid & 7) * 4;
    const int py = tid >> 3;
    const int gx0 = tx * 32 - 1;
    const int gy0 = ty * 16 - 1;

    auto load_tile = [&](int ci, int b) {
        const float* ip = in + ((size_t)n * CI + ci) * (size_t)H * W;
        for (int i = tid; i < 18 * 34; i += 128) {
            int r = i / 34, c = i - r * 34;
            int gy = gy0 + r, gx = gx0 + c;
            float v = 0.f;
            if (gy >= 0 && gy < H && gx >= 0 && gx < W) v = ip[(size_t)gy * W + gx];
            s_in[b][r][c] = v;
        }
    };

    float acc[16][4];
    #pragma unroll
    for (int co = 0; co < 16; co++)
        #pragma unroll
        for (int p = 0; p < 4; p++) acc[co][p] = 0.f;

    load_tile(0, 0);
    __syncthreads();

    for (int ci = 0; ci < CI; ci++) {
        const int cur = ci & 1;
        if (ci + 1 < CI) load_tile(ci + 1, cur ^ 1);

        float iv[3][6];
        #pragma unroll
        for (int ky = 0; ky < 3; ky++)
            #pragma unroll
            for (int j = 0; j < 6; j++)
                iv[ky][j] = s_in[cur][py + ky][px + j];

        #pragma unroll
        for (int co = 0; co < 16; co++) {
            const float* wp = &s_w[(co * CI + ci) * 9];
            #pragma unroll
            for (int ky = 0; ky < 3; ky++)
                #pragma unroll
                for (int kx = 0; kx < 3; kx++) {
                    float wv = wp[ky * 3 + kx];
                    #pragma unroll
                    for (int p = 0; p < 4; p++)
                        acc[co][p] = fmaf(iv[ky][kx + p], wv, acc[co][p]);
                }
        }
        __syncthreads();
    }

    const int y = ty * 16 + py;
    const bool yv = (y < H);
    #pragma unroll
    for (int co = 0; co < 16; co++) {
        int cg = cog * 16 + co;
        float b = bias[cg];
        size_t base = (((size_t)n * CO + cg) * H + y) * (size_t)W;
        float s = 0.f, q = 0.f;
        #pragma unroll
        for (int p = 0; p < 4; p++) {
            int x = tx * 32 + px + p;
            float v = acc[co][p] + b;
            bool valid = yv && (x < W);
            if (STORE && valid) out[base + x] = v;
            if (valid) { s += v; q += v * v; }
        }
        #pragma unroll
        for (int o = 16; o > 0; o >>= 1) {
            s += __shfl_down_sync(0xffffffffu, s, o);
            q += __shfl_down_sync(0xffffffffu, q, o);
        }
        if (lane == 0) { redS[co][warp] = s; redQ[co][warp] = q; }
    }
    __syncthreads();
    if (tid < 16) {
        float S = redS[tid][0] + redS[tid][1] + redS[tid][2] + redS[tid][3];
        float Q = redQ[tid][0] + redQ[tid][1] + redQ[tid][2] + redQ[tid][3];
        int slot = (blockIdx.x + blockIdx.z * 977) & 511;
        int c = cog * 16 + tid;
        atomicAdd(&g_psum[(layer * 64 + c) * 512 + slot], S);
        atomicAdd(&g_psumsq[(layer * 64 + c) * 512 + slot], Q);
    }
}

// ---------------- layer1 fused: conv(1->16) + BN + ReLU + pool2 --------------
__launch_bounds__(128)
__global__ void conv1_pool_k(const float* __restrict__ in, const float* __restrict__ w,
                             const float* __restrict__ bias, float* __restrict__ out) {
    const int H = 224, W = 224;
    __shared__ float s_in[34][35];
    __shared__ float s_w[16 * 9];
    __shared__ float s_a[16], s_t[16];
    const int n = blockIdx.z;
    const int tx = blockIdx.x % 7, ty = blockIdx.x / 7;
    const int tid = threadIdx.x;

    for (int i = tid; i < 144; i += 128) s_w[i] = w[i];
    if (tid < 16) {
        float a = g_scale[tid];
        s_a[tid] = a;
        s_t[tid] = bias[tid] * a + g_shift[tid];
    }
    const int gx0 = tx * 32 - 1, gy0 = ty * 32 - 1;
    const float* ip = in + (size_t)n * H * W;
    for (int i = tid; i < 34 * 34; i += 128) {
        int r = i / 34, c = i % 34;
        int gy = gy0 + r, gx = gx0 + c;
        float v = 0.f;
        if (gy >= 0 && gy < H && gx >= 0 && gx < W) v = ip[(size_t)gy * W + gx];
        s_in[r][c] = v;
    }
    __syncthreads();

    const int pxp = (tid & 7) * 2;
    const int pyp = tid >> 3;
    const int cx = pxp * 2;
    const int cy = pyp * 2;

    float iv[4][6];
    #pragma unroll
    for (int r = 0; r < 4; r++)
        #pragma unroll
        for (int c = 0; c < 6; c++)
            iv[r][c] = s_in[cy + r][cx + c];

    const int gxp = tx * 16 + pxp;
    const int gyp = ty * 16 + pyp;

    #pragma unroll
    for (int co = 0; co < 16; co++) {
        float w0 = s_w[co * 9 + 0], w1 = s_w[co * 9 + 1], w2 = s_w[co * 9 + 2];
        float w3 = s_w[co * 9 + 3], w4 = s_w[co * 9 + 4], w5 = s_w[co * 9 + 5];
        float w6 = s_w[co * 9 + 6], w7 = s_w[co * 9 + 7], w8 = s_w[co * 9 + 8];
        float a = s_a[co], t = s_t[co];
        float v[2][4];
        #pragma unroll
        for (int r = 0; r < 2; r++)
            #pragma unroll
            for (int c = 0; c < 4; c++) {
                float s = iv[r + 0][c + 0] * w0 + iv[r + 0][c + 1] * w1 + iv[r + 0][c + 2] * w2
                        + iv[r + 1][c + 0] * w3 + iv[r + 1][c + 1] * w4 + iv[r + 1][c + 2] * w5
                        + iv[r + 2][c + 0] * w6 + iv[r + 2][c + 1] * w7 + iv[r + 2][c + 2] * w8;
                v[r][c] = fmaf(s, a, t);
            }
        float p0 = fmaxf(fmaxf(v[0][0], v[0][1]), fmaxf(v[1][0], v[1][1]));
        float p1 = fmaxf(fmaxf(v[0][2], v[0][3]), fmaxf(v[1][2], v[1][3]));
        size_t base = (((size_t)n * 16 + co) * 112 + gyp) * (size_t)112 + gxp;
        out[base + 0] = fmaxf(p0, 0.f);
        out[base + 1] = fmaxf(p1, 0.f);
    }
}

// ---------------- BN affine + ReLU + 2x2 maxpool (layers 2,3) ----------------
__global__ void bn_relu_pool_k(const float* __restrict__ in, float* __restrict__ out,
                               int C, int H, int W, long long total) {
    long long idx = (long long)blockIdx.x * blockDim.x + threadIdx.x;
    if (idx >= total) return;
    int W2 = W >> 1, H2 = H >> 1;
    int x2 = (int)(idx % W2);
    long long r = idx / W2;
    int y2 = (int)(r % H2); r /= H2;
    int c  = (int)(r % C);
    int n  = (int)(r / C);
    const float2* p0 = (const float2*)(in + (((size_t)n * C + c) * H + 2 * y2) * (size_t)W) + x2;
    const float2* p1 = (const float2*)((const float*)p0 + W);
    float2 u = *p0, d = *p1;
    float a = g_scale[c], s = g_shift[c];
    float v0 = fmaf(u.x, a, s);
    float v1 = fmaf(u.y, a, s);
    float v2 = fmaf(d.x, a, s);
    float v3 = fmaf(d.y, a, s);
    float m = fmaxf(fmaxf(v0, v1), fmaxf(v2, v3));
    out[idx] = fmaxf(m, 0.f);
}

// ---------------- head: GAP + fc1 + LN + quantum circuit + fc2/fc3 -----------
__global__ void head_k(const float* __restrict__ pooled,   // (B,64,28,28)
                       const float* __restrict__ fc1_w, const float* __restrict__ fc1_b,
                       const float* __restrict__ ln_g,  const float* __restrict__ ln_b,
                       const float* __restrict__ qp,
                       const float* __restrict__ fc2_w, const float* __restrict__ fc2_b,
                       const float* __restrict__ fc3_w, const float* __restrict__ fc3_b,
                       float* __restrict__ out) {
    const int n = blockIdx.x;
    const int tid = threadIdx.x;
    const int warp = tid >> 5, lane = tid & 31;
    __shared__ float chm[64];
    __shared__ float qin[5];
    __shared__ float qres;

    const float* base = pooled + (size_t)n * 64 * 784;
    for (int j = 0; j < 8; j++) {
        int c = warp * 8 + j;
        const float* p = base + (size_t)c * 784;
        float s = 0.f;
        for (int i = lane; i < 784; i += 32) s += p[i];
        #pragma unroll
        for (int o = 16; o > 0; o >>= 1) s += __shfl_down_sync(0xffffffffu, s, o);
        if (lane == 0) chm[c] = s * (1.0f / 784.0f);
    }
    __syncthreads();

    if (tid == 0) {
        float h[5];
        #pragma unroll
        for (int o = 0; o < 5; o++) {
            float s = fc1_b[o];
            for (int i = 0; i < 64; i++) s += chm[i] * fc1_w[i * 5 + o];
            h[o] = s;
        }
        float mu = 0.f;
        #pragma unroll
        for (int o = 0; o < 5; o++) mu += h[o];
        mu *= 0.2f;
        float var = 0.f;
        #pragma unroll
        for (int o = 0; o < 5; o++) { float d = h[o] - mu; var += d * d; }
        var *= 0.2f;
        float r = rsqrtf(var + 1e-5f);
        #pragma unroll
        for (int o = 0; o < 5; o++) qin[o] = ln_g[o] * (h[o] - mu) * r + ln_b[o];
    }
    __syncthreads();

    // 5-qubit statevector: amplitude per lane (warp 0). wire i -> bit (1<<(4-i))
    if (warp == 0) {
        float are = (lane == 0) ? 1.f : 0.f, aim = 0.f;
        const unsigned fm = 0xffffffffu;
        for (int l = 0; l < 3; l++) {
            #pragma unroll
            for (int i = 0; i < 5; i++) {
                int m = 1 << (4 - i);
                float sn, cs; sincosf(qin[i] * 0.5f, &sn, &cs);
                float pre = __shfl_xor_sync(fm, are, m);
                float pim = __shfl_xor_sync(fm, aim, m);
                float nre = cs * are + sn * pim;
                float nim = cs * aim - sn * pre;
                are = nre; aim = nim;
            }
            #pragma unroll
            for (int i = 0; i < 5; i++) {
                int m = 1 << (4 - i);
                float sy, cy; sincosf(qp[l * 10 + i] * 0.5f, &sy, &cy);
                float pre = __shfl_xor_sync(fm, are, m);
                float pim = __shfl_xor_sync(fm, aim, m);
                float sgn = (lane & m) ? sy : -sy;
                float nre = cy * are + sgn * pre;
                float nim = cy * aim + sgn * pim;
                float sz, cz; sincosf(qp[l * 10 + i + 5] * 0.5f, &sz, &cz);
                float zg = (lane & m) ? -sz : sz;
                are = nre * cz + zg * nim;
                aim = nim * cz - zg * nre;
            }
            const int cw[5] = {0, 1, 2, 3, 4};
            const int tw[5] = {1, 2, 3, 4, 0};
            #pragma unroll
            for (int k = 0; k < 5; k++) {
                int mc = 1 << (4 - cw[k]);
                int mt = 1 << (4 - tw[k]);
                int src = (lane & mc) ? (lane ^ mt) : lane;
                are = __shfl_sync(fm, are, src);
                aim = __shfl_sync(fm, aim, src);
            }
        }
        float p = are * are + aim * aim;
        float sgn = (__popc(lane & 28) & 1) ? -1.f : 1.f;
        float v = p * sgn;
        #pragma unroll
        for (int o = 16; o > 0; o >>= 1) v += __shfl_down_sync(fm, v, o);
        if (lane == 0) qres = v;
    }
    __syncthreads();

    if (tid == 0) {
        float q = qres;
        float l0 = fc3_b[0], l1 = fc3_b[1];
        for (int j = 0; j < 32; j++) {
            float h2 = fmaxf(q * fc2_w[j] + fc2_b[j], 0.f);
            l0 += h2 * fc3_w[j * 2 + 0];
            l1 += h2 * fc3_w[j * 2 + 1];
        }
        float mx = fmaxf(l0, l1);
        float lse = mx + logf(expf(l0 - mx) + expf(l1 - mx));
        out[n * 2 + 0] = l0 - lse;
        out[n * 2 + 1] = l1 - lse;
    }
}

// ---------------- host launcher ----------------------------------------------
extern "C" void kernel_launch(void* const* d_in, const int* in_sizes, int n_in,
                              void* d_out, int out_size) {
    const float* x    = (const float*)d_in[0];
    const float* c1w  = (const float*)d_in[1];
    const float* c1b  = (const float*)d_in[2];
    const float* bn1g = (const float*)d_in[3];
    const float* bn1b = (const float*)d_in[4];
    const float* c2w  = (const float*)d_in[5];
    const float* c2b  = (const float*)d_in[6];
    const float* bn2g = (const float*)d_in[7];
    const float* bn2b = (const float*)d_in[8];
    const float* c3w  = (const float*)d_in[9];
    const float* c3b  = (const float*)d_in[10];
    const float* bn3g = (const float*)d_in[11];
    const float* bn3b = (const float*)d_in[12];
    const float* fc1w = (const float*)d_in[13];
    const float* fc1b = (const float*)d_in[14];
    const float* lng  = (const float*)d_in[15];
    const float* lnb  = (const float*)d_in[16];
    const float* qp   = (const float*)d_in[17];
    const float* fc2w = (const float*)d_in[18];
    const float* fc2b = (const float*)d_in[19];
    const float* fc3w = (const float*)d_in[20];
    const float* fc3b = (const float*)d_in[21];
    float* out = (float*)d_out;

    float *conv, *poolA, *poolB;
    uint32_t *wT2, *wT3;
    cudaGetSymbolAddress((void**)&conv,  g_conv);
    cudaGetSymbolAddress((void**)&poolA, g_poolA);
    cudaGetSymbolAddress((void**)&poolB, g_poolB);
    cudaGetSymbolAddress((void**)&wT2, g_wT2);
    cudaGetSymbolAddress((void**)&wT3, g_wT3);

    const int B = 256;

    zero_partials_k<<<(3 * 64 * 512 + 511) / 512, 512>>>();
    wprep_k<<<(9 * 32 * 64 + 255) / 256, 256>>>(c2w, c3w);

    // ---- Layer 1: conv(1->16) @224, scalar stats pass + fused pool pass ----
    {
        int H = 224, W = 224, CO = 16;
        int txs = (W + 31) / 32, tys = (H + 15) / 16;
        conv3x3_k<1, false><<<dim3(txs * tys, 1, B), 128>>>(x, c1w, c1b, nullptr, CO, H, W, txs, 0);
        finalize_k<<<1, 64>>>(bn1g, bn1b, CO, 0, 1.0 / ((double)B * H * W));
        conv1_pool_k<<<dim3(49, 1, B), 128>>>(x, c1w, c1b, poolA);
    }
    // ---- Layer 2: conv(16->32) @112, TF32 tensor path ----
    {
        int H = 112, W = 112, CO = 32;
        conv_mma_k<16, 32><<<dim3(7 * 7, 1, B), 256>>>(poolA, wT2, c2b, conv, H, W, 7, 1);
        finalize_k<<<1, 64>>>(bn2g, bn2b, CO, 1, 1.0 / ((double)B * H * W));
        long long tot = (long long)B * CO * (H / 2) * (W / 2);
        bn_relu_pool_k<<<(unsigned)((tot + 255) / 256), 256>>>(conv, poolB, CO, H, W, tot);
    }
    // ---- Layer 3: conv(32->64) @56, TF32 tensor path ----
    {
        int H = 56, W = 56, CO = 64;
        conv_mma_k<32, 64><<<dim3(4 * 4, 1, B), 256>>>(poolB, wT3, c3b, conv, H, W, 4, 2);
        finalize_k<<<1, 64>>>(bn3g, bn3b, CO, 2, 1.0 / ((double)B * H * W));
        long long tot = (long long)B * CO * (H / 2) * (W / 2);
        bn_relu_pool_k<<<(unsigned)((tot + 255) / 256), 256>>>(conv, poolA, CO, H, W, tot);
    }
    // ---- Head ----
    head_k<<<B, 256>>>(poolA, fc1w, fc1b, lng, lnb, qp, fc2w, fc2b, fc3w, fc3b, out);
}

// round 8
// speedup vs baseline: 2.6480x; 1.1703x over previous
#include <cuda_runtime.h>
#include <math.h>
#include <stdint.h>

// ---------------- scratch (static device memory; no allocs allowed) ----------
__device__ float g_conv[102760448];   // max stored conv out: 256*32*112*112 (411 MB)
__device__ float g_poolA[51380224];   // 256*16*112*112 (205 MB); also pool3 out (51 MB)
__device__ float g_poolB[25690112];   // 256*32*56*56  (103 MB)
__device__ float g_psum[3 * 64 * 512];
__device__ float g_psumsq[3 * 64 * 512];
__device__ float g_scale[64];
__device__ float g_shift[64];
__device__ uint32_t g_wT2[9 * 16 * 32];   // tf32 weights [tap][ci][co]
__device__ uint32_t g_wT3[9 * 32 * 64];

__device__ __forceinline__ uint32_t f2tf32(float v) {
    uint32_t t; asm("cvt.rna.tf32.f32 %0, %1;" : "=r"(t) : "f"(v));
    return t;
}

// ---------------- zero partial-stat buffers ----------------------------------
__global__ void zero_partials_k() {
    int i = blockIdx.x * blockDim.x + threadIdx.x;
    if (i < 3 * 64 * 512) { g_psum[i] = 0.f; g_psumsq[i] = 0.f; }
}

// ---------------- weight transpose + tf32 round prep --------------------------
__global__ void wprep_k(const float* __restrict__ w2, const float* __restrict__ w3) {
    int i = blockIdx.x * 256 + threadIdx.x;
    if (i < 9 * 16 * 32) {
        int co = i / 144, rem = i - co * 144, ci = rem / 9, tap = rem - ci * 9;
        g_wT2[(tap * 16 + ci) * 32 + co] = f2tf32(w2[i]);
    }
    if (i < 9 * 32 * 64) {
        int co = i / 288, rem = i - co * 288, ci = rem / 9, tap = rem - ci * 9;
        g_wT3[(tap * 32 + ci) * 64 + co] = f2tf32(w3[i]);
    }
}

// ---------------- finalize: parallel reduce partials -> scale/shift -----------
// grid = C blocks, block = 32 lanes: each lane sums 16 slots, warp-reduce.
__global__ void finalize_k(const float* __restrict__ gam, const float* __restrict__ bet,
                           int layer, double inv_cnt) {
    int c = blockIdx.x;
    int lane = threadIdx.x;
    const float* ps = &g_psum[(layer * 64 + c) * 512];
    const float* pq = &g_psumsq[(layer * 64 + c) * 512];
    double S = 0.0, Q = 0.0;
    #pragma unroll
    for (int i = 0; i < 16; i++) {
        S += (double)ps[lane + i * 32];
        Q += (double)pq[lane + i * 32];
    }
    #pragma unroll
    for (int o = 16; o > 0; o >>= 1) {
        S += __shfl_down_sync(0xffffffffu, S, o);
        Q += __shfl_down_sync(0xffffffffu, Q, o);
    }
    if (lane == 0) {
        double mean = S * inv_cnt;
        double var = Q * inv_cnt - mean * mean;
        float sc = gam[c] * rsqrtf((float)var + 1e-5f);
        g_scale[c] = sc;
        g_shift[c] = bet[c] - sc * (float)mean;
    }
}

// ---------------- TF32 tensor-core shift-GEMM 3x3 conv + fused BN stats ------
// Block 256 thr (8 warps). Spatial tile 16x16. mma.m16n8k8: M=16 px of one row,
// N=8 output channels, K=8 input channels; 9 taps = 9 shifted GEMMs.
template<int CI, int CO>
__launch_bounds__(256)
__global__ void conv_mma_k(const float* __restrict__ in, const uint32_t* __restrict__ wT,
                           const float* __restrict__ bias, float* __restrict__ out,
                           int H, int W, int tiles_x, int layer) {
    constexpr int CIP = (CI == 32) ? 36 : 20;   // bank-conflict-free pitch
    constexpr int KS  = CI / 8;
    constexpr int NT  = CO / 8;                 // n-tiles
    constexpr int MSEG = 8 / NT;                // warps per ntile (m split)
    constexpr int MT_PER = 16 / MSEG;
    __shared__ uint32_t s_in[18][18][CIP];

    const int n = blockIdx.z;
    const int tile = blockIdx.x;
    const int tx0 = (tile % tiles_x) * 16;
    const int ty0 = (tile / tiles_x) * 16;
    const int tid = threadIdx.x, warp = tid >> 5, lane = tid & 31;

    // ---- load 18x18xCI halo tile (channel-last, tf32-rounded) ----
    const int gx0 = tx0 - 1, gy0 = ty0 - 1;
    for (int i = tid; i < CI * 324; i += 256) {
        int ci = i / 324, rem = i - ci * 324;
        int r = rem / 18, c = rem - r * 18;
        int gy = gy0 + r, gx = gx0 + c;
        float v = 0.f;
        if (gy >= 0 && gy < H && gx >= 0 && gx < W)
            v = in[((size_t)n * CI + ci) * (size_t)(H * W) + (size_t)gy * W + gx];
        s_in[r][c][ci] = f2tf32(v);
    }

    const int ntile = warp % NT;
    const int mseg  = warp / NT;
    const int ci_lo = lane & 3;
    const int xA    = lane >> 2;

    // ---- preload B fragments into registers ----
    uint32_t breg[9][KS][2];
    #pragma unroll
    for (int tap = 0; tap < 9; tap++)
        #pragma unroll
        for (int ks = 0; ks < KS; ks++) {
            breg[tap][ks][0] = wT[(tap * CI + ks * 8 + ci_lo) * CO + ntile * 8 + xA];
            breg[tap][ks][1] = wT[(tap * CI + ks * 8 + ci_lo + 4) * CO + ntile * 8 + xA];
        }
    const int co_e = ntile * 8 + 2 * ci_lo;     // this lane's channel pair
    const float b_lo = bias[co_e], b_hi = bias[co_e + 1];

    __syncthreads();

    float sA = 0.f, qA = 0.f, sB = 0.f, qB = 0.f;
    const size_t chan_stride = (size_t)H * W;

    for (int mi = 0; mi < MT_PER; mi++) {
        int mt = mseg * MT_PER + mi;            // row within tile
        int y = ty0 + mt;
        if (y >= H) break;
        float c0 = 0.f, c1 = 0.f, c2 = 0.f, c3 = 0.f;
        #pragma unroll
        for (int tap = 0; tap < 9; tap++) {
            const int ky = tap / 3, kx = tap - ky * 3;
            #pragma unroll
            for (int ks = 0; ks < KS; ks++) {
                uint32_t a0 = s_in[mt + ky][xA + kx][ks * 8 + ci_lo];
                uint32_t a1 = s_in[mt + ky][xA + 8 + kx][ks * 8 + ci_lo];
                uint32_t a2 = s_in[mt + ky][xA + kx][ks * 8 + ci_lo + 4];
                uint32_t a3 = s_in[mt + ky][xA + 8 + kx][ks * 8 + ci_lo + 4];
                asm volatile(
                    "mma.sync.aligned.m16n8k8.row.col.f32.tf32.tf32.f32 "
                    "{%0,%1,%2,%3}, {%4,%5,%6,%7}, {%8,%9}, {%0,%1,%2,%3};"
                    : "+f"(c0), "+f"(c1), "+f"(c2), "+f"(c3)
                    : "r"(a0), "r"(a1), "r"(a2), "r"(a3),
                      "r"(breg[tap][ks][0]), "r"(breg[tap][ks][1]));
            }
        }
        // epilogue: bias + masked store + stats
        int x_lo = tx0 + xA, x_hi = x_lo + 8;
        size_t base = (((size_t)n * CO + co_e) * H + y) * (size_t)W;
        float v00 = c0 + b_lo, v01 = c1 + b_hi, v10 = c2 + b_lo, v11 = c3 + b_hi;
        if (x_lo < W) {
            out[base + x_lo] = v00;
            out[base + chan_stride + x_lo] = v01;
            sA += v00; qA += v00 * v00; sB += v01; qB += v01 * v01;
        }
        if (x_hi < W) {
            out[base + x_hi] = v10;
            out[base + chan_stride + x_hi] = v11;
            sA += v10; qA += v10 * v10; sB += v11; qB += v11 * v11;
        }
    }

    // reduce stats across the 8 lanes sharing (lane&3), then atomically scatter
    #pragma unroll
    for (int off = 4; off < 32; off <<= 1) {
        sA += __shfl_xor_sync(0xffffffffu, sA, off);
        qA += __shfl_xor_sync(0xffffffffu, qA, off);
        sB += __shfl_xor_sync(0xffffffffu, sB, off);
        qB += __shfl_xor_sync(0xffffffffu, qB, off);
    }
    if (lane < 4) {
        int slot = (blockIdx.x + blockIdx.z * 977 + warp * 53) & 511;
        atomicAdd(&g_psum  [(layer * 64 + co_e) * 512 + slot], sA);
        atomicAdd(&g_psumsq[(layer * 64 + co_e) * 512 + slot], qA);
        atomicAdd(&g_psum  [(layer * 64 + co_e + 1) * 512 + slot], sB);
        atomicAdd(&g_psumsq[(layer * 64 + co_e + 1) * 512 + slot], qB);
    }
}

// ---------------- layer1 stats: scalar direct conv (CI=1), no store ----------
template<int CI, bool STORE>
__launch_bounds__(128)
__global__ void conv3x3_k(const float* __restrict__ in, const float* __restrict__ w,
                          const float* __restrict__ bias, float* __restrict__ out,
                          int CO, int H, int W, int tiles_x, int layer) {
    __shared__ float s_in[2][18][36];
    __shared__ float s_w[CI * 16 * 9];
    __shared__ float redS[16][4], redQ[16][4];
    const int n   = blockIdx.z;
    const int cog = blockIdx.y;
    const int tile = blockIdx.x;
    const int tx = tile % tiles_x, ty = tile / tiles_x;
    const int tid = threadIdx.x;
    const int warp = tid >> 5, lane = tid & 31;

    for (int i = tid; i < CI * 16 * 9; i += 128)
        s_w[i] = w[(size_t)(cog * 16) * CI * 9 + i];

    const int px = (tid & 7) * 4;
    const int py = tid >> 3;
    const int gx0 = tx * 32 - 1;
    const int gy0 = ty * 16 - 1;

    auto load_tile = [&](int ci, int b) {
        const float* ip = in + ((size_t)n * CI + ci) * (size_t)H * W;
        for (int i = tid; i < 18 * 34; i += 128) {
            int r = i / 34, c = i - r * 34;
            int gy = gy0 + r, gx = gx0 + c;
            float v = 0.f;
            if (gy >= 0 && gy < H && gx >= 0 && gx < W) v = ip[(size_t)gy * W + gx];
            s_in[b][r][c] = v;
        }
    };

    float acc[16][4];
    #pragma unroll
    for (int co = 0; co < 16; co++)
        #pragma unroll
        for (int p = 0; p < 4; p++) acc[co][p] = 0.f;

    load_tile(0, 0);
    __syncthreads();

    for (int ci = 0; ci < CI; ci++) {
        const int cur = ci & 1;
        if (ci + 1 < CI) load_tile(ci + 1, cur ^ 1);

        float iv[3][6];
        #pragma unroll
        for (int ky = 0; ky < 3; ky++)
            #pragma unroll
            for (int j = 0; j < 6; j++)
                iv[ky][j] = s_in[cur][py + ky][px + j];

        #pragma unroll
        for (int co = 0; co < 16; co++) {
            const float* wp = &s_w[(co * CI + ci) * 9];
            #pragma unroll
            for (int ky = 0; ky < 3; ky++)
                #pragma unroll
                for (int kx = 0; kx < 3; kx++) {
                    float wv = wp[ky * 3 + kx];
                    #pragma unroll
                    for (int p = 0; p < 4; p++)
                        acc[co][p] = fmaf(iv[ky][kx + p], wv, acc[co][p]);
                }
        }
        __syncthreads();
    }

    const int y = ty * 16 + py;
    const bool yv = (y < H);
    #pragma unroll
    for (int co = 0; co < 16; co++) {
        int cg = cog * 16 + co;
        float b = bias[cg];
        size_t base = (((size_t)n * CO + cg) * H + y) * (size_t)W;
        float s = 0.f, q = 0.f;
        #pragma unroll
        for (int p = 0; p < 4; p++) {
            int x = tx * 32 + px + p;
            float v = acc[co][p] + b;
            bool valid = yv && (x < W);
            if (STORE && valid) out[base + x] = v;
            if (valid) { s += v; q += v * v; }
        }
        #pragma unroll
        for (int o = 16; o > 0; o >>= 1) {
            s += __shfl_down_sync(0xffffffffu, s, o);
            q += __shfl_down_sync(0xffffffffu, q, o);
        }
        if (lane == 0) { redS[co][warp] = s; redQ[co][warp] = q; }
    }
    __syncthreads();
    if (tid < 16) {
        float S = redS[tid][0] + redS[tid][1] + redS[tid][2] + redS[tid][3];
        float Q = redQ[tid][0] + redQ[tid][1] + redQ[tid][2] + redQ[tid][3];
        int slot = (blockIdx.x + blockIdx.z * 977) & 511;
        int c = cog * 16 + tid;
        atomicAdd(&g_psum[(layer * 64 + c) * 512 + slot], S);
        atomicAdd(&g_psumsq[(layer * 64 + c) * 512 + slot], Q);
    }
}

// ---------------- layer1 fused: conv(1->16) + BN + ReLU + pool2 --------------
__launch_bounds__(128)
__global__ void conv1_pool_k(const float* __restrict__ in, const float* __restrict__ w,
                             const float* __restrict__ bias, float* __restrict__ out) {
    const int H = 224, W = 224;
    __shared__ float s_in[34][35];
    __shared__ float s_w[16 * 9];
    __shared__ float s_a[16], s_t[16];
    const int n = blockIdx.z;
    const int tx = blockIdx.x % 7, ty = blockIdx.x / 7;
    const int tid = threadIdx.x;

    for (int i = tid; i < 144; i += 128) s_w[i] = w[i];
    if (tid < 16) {
        float a = g_scale[tid];
        s_a[tid] = a;
        s_t[tid] = bias[tid] * a + g_shift[tid];
    }
    const int gx0 = tx * 32 - 1, gy0 = ty * 32 - 1;
    const float* ip = in + (size_t)n * H * W;
    for (int i = tid; i < 34 * 34; i += 128) {
        int r = i / 34, c = i % 34;
        int gy = gy0 + r, gx = gx0 + c;
        float v = 0.f;
        if (gy >= 0 && gy < H && gx >= 0 && gx < W) v = ip[(size_t)gy * W + gx];
        s_in[r][c] = v;
    }
    __syncthreads();

    const int pxp = (tid & 7) * 2;
    const int pyp = tid >> 3;
    const int cx = pxp * 2;
    const int cy = pyp * 2;

    float iv[4][6];
    #pragma unroll
    for (int r = 0; r < 4; r++)
        #pragma unroll
        for (int c = 0; c < 6; c++)
            iv[r][c] = s_in[cy + r][cx + c];

    const int gxp = tx * 16 + pxp;
    const int gyp = ty * 16 + pyp;

    #pragma unroll
    for (int co = 0; co < 16; co++) {
        float w0 = s_w[co * 9 + 0], w1 = s_w[co * 9 + 1], w2 = s_w[co * 9 + 2];
        float w3 = s_w[co * 9 + 3], w4 = s_w[co * 9 + 4], w5 = s_w[co * 9 + 5];
        float w6 = s_w[co * 9 + 6], w7 = s_w[co * 9 + 7], w8 = s_w[co * 9 + 8];
        float a = s_a[co], t = s_t[co];
        float v[2][4];
        #pragma unroll
        for (int r = 0; r < 2; r++)
            #pragma unroll
            for (int c = 0; c < 4; c++) {
                float s = iv[r + 0][c + 0] * w0 + iv[r + 0][c + 1] * w1 + iv[r + 0][c + 2] * w2
                        + iv[r + 1][c + 0] * w3 + iv[r + 1][c + 1] * w4 + iv[r + 1][c + 2] * w5
                        + iv[r + 2][c + 0] * w6 + iv[r + 2][c + 1] * w7 + iv[r + 2][c + 2] * w8;
                v[r][c] = fmaf(s, a, t);
            }
        float p0 = fmaxf(fmaxf(v[0][0], v[0][1]), fmaxf(v[1][0], v[1][1]));
        float p1 = fmaxf(fmaxf(v[0][2], v[0][3]), fmaxf(v[1][2], v[1][3]));
        size_t base = (((size_t)n * 16 + co) * 112 + gyp) * (size_t)112 + gxp;
        out[base + 0] = fmaxf(p0, 0.f);
        out[base + 1] = fmaxf(p1, 0.f);
    }
}

// ---------------- BN affine + ReLU + 2x2 maxpool (layers 2,3) ----------------
__global__ void bn_relu_pool_k(const float* __restrict__ in, float* __restrict__ out,
                               int C, int H, int W, long long total) {
    long long idx = (long long)blockIdx.x * blockDim.x + threadIdx.x;
    if (idx >= total) return;
    int W2 = W >> 1, H2 = H >> 1;
    int x2 = (int)(idx % W2);
    long long r = idx / W2;
    int y2 = (int)(r % H2); r /= H2;
    int c  = (int)(r % C);
    int n  = (int)(r / C);
    const float2* p0 = (const float2*)(in + (((size_t)n * C + c) * H + 2 * y2) * (size_t)W) + x2;
    const float2* p1 = (const float2*)((const float*)p0 + W);
    float2 u = *p0, d = *p1;
    float a = g_scale[c], s = g_shift[c];
    float v0 = fmaf(u.x, a, s);
    float v1 = fmaf(u.y, a, s);
    float v2 = fmaf(d.x, a, s);
    float v3 = fmaf(d.y, a, s);
    float m = fmaxf(fmaxf(v0, v1), fmaxf(v2, v3));
    out[idx] = fmaxf(m, 0.f);
}

// ---------------- head: GAP + fc1 + LN + quantum circuit + fc2/fc3 -----------
__global__ void head_k(const float* __restrict__ pooled,   // (B,64,28,28)
                       const float* __restrict__ fc1_w, const float* __restrict__ fc1_b,
                       const float* __restrict__ ln_g,  const float* __restrict__ ln_b,
                       const float* __restrict__ qp,
                       const float* __restrict__ fc2_w, const float* __restrict__ fc2_b,
                       const float* __restrict__ fc3_w, const float* __restrict__ fc3_b,
                       float* __restrict__ out) {
    const int n = blockIdx.x;
    const int tid = threadIdx.x;
    const int warp = tid >> 5, lane = tid & 31;
    __shared__ float chm[64];
    __shared__ float qin[5];
    __shared__ float qres;

    const float* base = pooled + (size_t)n * 64 * 784;
    for (int j = 0; j < 8; j++) {
        int c = warp * 8 + j;
        const float* p = base + (size_t)c * 784;
        float s = 0.f;
        for (int i = lane; i < 784; i += 32) s += p[i];
        #pragma unroll
        for (int o = 16; o > 0; o >>= 1) s += __shfl_down_sync(0xffffffffu, s, o);
        if (lane == 0) chm[c] = s * (1.0f / 784.0f);
    }
    __syncthreads();

    if (tid == 0) {
        float h[5];
        #pragma unroll
        for (int o = 0; o < 5; o++) {
            float s = fc1_b[o];
            for (int i = 0; i < 64; i++) s += chm[i] * fc1_w[i * 5 + o];
            h[o] = s;
        }
        float mu = 0.f;
        #pragma unroll
        for (int o = 0; o < 5; o++) mu += h[o];
        mu *= 0.2f;
        float var = 0.f;
        #pragma unroll
        for (int o = 0; o < 5; o++) { float d = h[o] - mu; var += d * d; }
        var *= 0.2f;
        float r = rsqrtf(var + 1e-5f);
        #pragma unroll
        for (int o = 0; o < 5; o++) qin[o] = ln_g[o] * (h[o] - mu) * r + ln_b[o];
    }
    __syncthreads();

    // 5-qubit statevector: amplitude per lane (warp 0). wire i -> bit (1<<(4-i))
    if (warp == 0) {
        float are = (lane == 0) ? 1.f : 0.f, aim = 0.f;
        const unsigned fm = 0xffffffffu;
        for (int l = 0; l < 3; l++) {
            #pragma unroll
            for (int i = 0; i < 5; i++) {
                int m = 1 << (4 - i);
                float sn, cs; sincosf(qin[i] * 0.5f, &sn, &cs);
                float pre = __shfl_xor_sync(fm, are, m);
                float pim = __shfl_xor_sync(fm, aim, m);
                float nre = cs * are + sn * pim;
                float nim = cs * aim - sn * pre;
                are = nre; aim = nim;
            }
            #pragma unroll
            for (int i = 0; i < 5; i++) {
                int m = 1 << (4 - i);
                float sy, cy; sincosf(qp[l * 10 + i] * 0.5f, &sy, &cy);
                float pre = __shfl_xor_sync(fm, are, m);
                float pim = __shfl_xor_sync(fm, aim, m);
                float sgn = (lane & m) ? sy : -sy;
                float nre = cy * are + sgn * pre;
                float nim = cy * aim + sgn * pim;
                float sz, cz; sincosf(qp[l * 10 + i + 5] * 0.5f, &sz, &cz);
                float zg = (lane & m) ? -sz : sz;
                are = nre * cz + zg * nim;
                aim = nim * cz - zg * nre;
            }
            const int cw[5] = {0, 1, 2, 3, 4};
            const int tw[5] = {1, 2, 3, 4, 0};
            #pragma unroll
            for (int k = 0; k < 5; k++) {
                int mc = 1 << (4 - cw[k]);
                int mt = 1 << (4 - tw[k]);
                int src = (lane & mc) ? (lane ^ mt) : lane;
                are = __shfl_sync(fm, are, src);
                aim = __shfl_sync(fm, aim, src);
            }
        }
        float p = are * are + aim * aim;
        float sgn = (__popc(lane & 28) & 1) ? -1.f : 1.f;
        float v = p * sgn;
        #pragma unroll
        for (int o = 16; o > 0; o >>= 1) v += __shfl_down_sync(fm, v, o);
        if (lane == 0) qres = v;
    }
    __syncthreads();

    if (tid == 0) {
        float q = qres;
        float l0 = fc3_b[0], l1 = fc3_b[1];
        for (int j = 0; j < 32; j++) {
            float h2 = fmaxf(q * fc2_w[j] + fc2_b[j], 0.f);
            l0 += h2 * fc3_w[j * 2 + 0];
            l1 += h2 * fc3_w[j * 2 + 1];
        }
        float mx = fmaxf(l0, l1);
        float lse = mx + logf(expf(l0 - mx) + expf(l1 - mx));
        out[n * 2 + 0] = l0 - lse;
        out[n * 2 + 1] = l1 - lse;
    }
}

// ---------------- host launcher ----------------------------------------------
extern "C" void kernel_launch(void* const* d_in, const int* in_sizes, int n_in,
                              void* d_out, int out_size) {
    const float* x    = (const float*)d_in[0];
    const float* c1w  = (const float*)d_in[1];
    const float* c1b  = (const float*)d_in[2];
    const float* bn1g = (const float*)d_in[3];
    const float* bn1b = (const float*)d_in[4];
    const float* c2w  = (const float*)d_in[5];
    const float* c2b  = (const float*)d_in[6];
    const float* bn2g = (const float*)d_in[7];
    const float* bn2b = (const float*)d_in[8];
    const float* c3w  = (const float*)d_in[9];
    const float* c3b  = (const float*)d_in[10];
    const float* bn3g = (const float*)d_in[11];
    const float* bn3b = (const float*)d_in[12];
    const float* fc1w = (const float*)d_in[13];
    const float* fc1b = (const float*)d_in[14];
    const float* lng  = (const float*)d_in[15];
    const float* lnb  = (const float*)d_in[16];
    const float* qp   = (const float*)d_in[17];
    const float* fc2w = (const float*)d_in[18];
    const float* fc2b = (const float*)d_in[19];
    const float* fc3w = (const float*)d_in[20];
    const float* fc3b = (const float*)d_in[21];
    float* out = (float*)d_out;

    float *conv, *poolA, *poolB;
    uint32_t *wT2, *wT3;
    cudaGetSymbolAddress((void**)&conv,  g_conv);
    cudaGetSymbolAddress((void**)&poolA, g_poolA);
    cudaGetSymbolAddress((void**)&poolB, g_poolB);
    cudaGetSymbolAddress((void**)&wT2, g_wT2);
    cudaGetSymbolAddress((void**)&wT3, g_wT3);

    const int B = 256;

    zero_partials_k<<<(3 * 64 * 512 + 511) / 512, 512>>>();
    wprep_k<<<(9 * 32 * 64 + 255) / 256, 256>>>(c2w, c3w);

    // ---- Layer 1: conv(1->16) @224, scalar stats pass + fused pool pass ----
    {
        int H = 224, W = 224, CO = 16;
        int txs = (W + 31) / 32, tys = (H + 15) / 16;
        conv3x3_k<1, false><<<dim3(txs * tys, 1, B), 128>>>(x, c1w, c1b, nullptr, CO, H, W, txs, 0);
        finalize_k<<<CO, 32>>>(bn1g, bn1b, 0, 1.0 / ((double)B * H * W));
        conv1_pool_k<<<dim3(49, 1, B), 128>>>(x, c1w, c1b, poolA);
    }
    // ---- Layer 2: conv(16->32) @112, TF32 tensor path ----
    {
        int H = 112, W = 112, CO = 32;
        conv_mma_k<16, 32><<<dim3(7 * 7, 1, B), 256>>>(poolA, wT2, c2b, conv, H, W, 7, 1);
        finalize_k<<<CO, 32>>>(bn2g, bn2b, 1, 1.0 / ((double)B * H * W));
        long long tot = (long long)B * CO * (H / 2) * (W / 2);
        bn_relu_pool_k<<<(unsigned)((tot + 255) / 256), 256>>>(conv, poolB, CO, H, W, tot);
    }
    // ---- Layer 3: conv(32->64) @56, TF32 tensor path ----
    {
        int H = 56, W = 56, CO = 64;
        conv_mma_k<32, 64><<<dim3(4 * 4, 1, B), 256>>>(poolB, wT3, c3b, conv, H, W, 4, 2);
        finalize_k<<<CO, 32>>>(bn3g, bn3b, 2, 1.0 / ((double)B * H * W));
        long long tot = (long long)B * CO * (H / 2) * (W / 2);
        bn_relu_pool_k<<<(unsigned)((tot + 255) / 256), 256>>>(conv, poolA, CO, H, W, tot);
    }
    // ---- Head ----
    head_k<<<B, 256>>>(poolA, fc1w, fc1b, lng, lnb, qp, fc2w, fc2b, fc3w, fc3b, out);
}

// round 9
// speedup vs baseline: 3.4430x; 1.3002x over previous
#include <cuda_runtime.h>
#include <cuda_bf16.h>
#include <math.h>
#include <stdint.h>

// ---------------- scratch (static device memory; no allocs allowed) ----------
__device__ float g_conv[102760448];   // max stored conv out: 256*32*112*112 (411 MB)
__device__ float g_poolA[51380224];   // 256*16*112*112 (205 MB); also pool3 out (51 MB)
__device__ float g_poolB[25690112];   // 256*32*56*56  (103 MB)
__device__ float g_psum[3 * 64 * 512];
__device__ float g_psumsq[3 * 64 * 512];
__device__ float g_scale[64];
__device__ float g_shift[64];
__device__ uint32_t g_wT2[9 * 8 * 32];    // bf16x2 weights [tap][ci/2][co]
__device__ uint32_t g_wT3[9 * 16 * 64];

__device__ __forceinline__ uint32_t pack_bf16x2(float lo, float hi) {
    uint32_t w;
    asm("cvt.rn.bf16x2.f32 %0, %1, %2;" : "=r"(w) : "f"(hi), "f"(lo));
    return w;
}

// ---------------- zero partial-stat buffers ----------------------------------
__global__ void zero_partials_k() {
    int i = blockIdx.x * blockDim.x + threadIdx.x;
    if (i < 3 * 64 * 512) { g_psum[i] = 0.f; g_psumsq[i] = 0.f; }
}

// ---------------- weight transpose + bf16 pack prep ---------------------------
__global__ void wprep_k(const float* __restrict__ w2, const float* __restrict__ w3) {
    int i = blockIdx.x * 256 + threadIdx.x;
    if (i < 9 * 8 * 32) {           // layer2: [tap][j=ci/2][co], CI=16, CO=32
        int co = i & 31, rem = i >> 5, j = rem % 8, tap = rem / 8;
        float lo = w2[co * 144 + (2 * j) * 9 + tap];
        float hi = w2[co * 144 + (2 * j + 1) * 9 + tap];
        g_wT2[(tap * 8 + j) * 32 + co] = pack_bf16x2(lo, hi);
    }
    if (i < 9 * 16 * 64) {          // layer3: CI=32, CO=64
        int co = i & 63, rem = i >> 6, j = rem % 16, tap = rem / 16;
        float lo = w3[co * 288 + (2 * j) * 9 + tap];
        float hi = w3[co * 288 + (2 * j + 1) * 9 + tap];
        g_wT3[(tap * 16 + j) * 64 + co] = pack_bf16x2(lo, hi);
    }
}

// ---------------- finalize: parallel reduce partials -> scale/shift -----------
__global__ void finalize_k(const float* __restrict__ gam, const float* __restrict__ bet,
                           int layer, double inv_cnt) {
    int c = blockIdx.x;
    int lane = threadIdx.x;
    const float* ps = &g_psum[(layer * 64 + c) * 512];
    const float* pq = &g_psumsq[(layer * 64 + c) * 512];
    double S = 0.0, Q = 0.0;
    #pragma unroll
    for (int i = 0; i < 16; i++) {
        S += (double)ps[lane + i * 32];
        Q += (double)pq[lane + i * 32];
    }
    #pragma unroll
    for (int o = 16; o > 0; o >>= 1) {
        S += __shfl_down_sync(0xffffffffu, S, o);
        Q += __shfl_down_sync(0xffffffffu, Q, o);
    }
    if (lane == 0) {
        double mean = S * inv_cnt;
        double var = Q * inv_cnt - mean * mean;
        float sc = gam[c] * rsqrtf((float)var + 1e-5f);
        g_scale[c] = sc;
        g_shift[c] = bet[c] - sc * (float)mean;
    }
}

// ---------------- BF16 tensor-core shift-GEMM 3x3 conv + fused BN stats ------
// Block 256 thr (8 warps). Tile 16(x) x TH(y). mma.m16n8k16.bf16:
// M=16 px of one row, N=8 out-chan, K=16 in-chan; 9 taps = 9 shifted GEMMs.
template<int CI, int CO, int TH>
__launch_bounds__(256)
__global__ void conv_mma_k(const float* __restrict__ in, const uint32_t* __restrict__ wT,
                           const float* __restrict__ bias, float* __restrict__ out,
                           int H, int W, int tiles_x, int layer) {
    constexpr int W2   = CI / 2;                  // packed words per pixel
    constexpr int CIP2 = (CI == 32) ? 20 : 12;    // conflict-free pitch
    constexpr int KS   = CI / 16;                 // k16 steps
    constexpr int NT   = CO / 8;
    constexpr int MSEG = 8 / NT;
    constexpr int MT_PER = TH / MSEG;
    constexpr int RHALO = TH + 2;
    __shared__ uint32_t s_in[RHALO][18][CIP2];

    const int n = blockIdx.z;
    const int tile = blockIdx.x;
    const int tx0 = (tile % tiles_x) * 16;
    const int ty0 = (tile / tiles_x) * TH;
    const int tid = threadIdx.x, warp = tid >> 5, lane = tid & 31;

    // ---- load halo tile (channel-pair packed bf16x2) ----
    const int gx0 = tx0 - 1, gy0 = ty0 - 1;
    const size_t HW = (size_t)H * W;
    for (int i = tid; i < RHALO * 18 * W2; i += 256) {
        int c = i % 18, rem = i / 18;
        int wi = rem % W2, r = rem / W2;
        int gy = gy0 + r, gx = gx0 + c;
        float v0 = 0.f, v1 = 0.f;
        if (gy >= 0 && gy < H && gx >= 0 && gx < W) {
            const float* p = in + ((size_t)n * CI + 2 * wi) * HW + (size_t)gy * W + gx;
            v0 = p[0];
            v1 = p[HW];
        }
        s_in[r][c][wi] = pack_bf16x2(v0, v1);
    }

    const int ntile = warp % NT;
    const int mseg  = warp / NT;
    const int ci_lo = lane & 3;     // j-word within k16 fragment
    const int xA    = lane >> 2;

    // ---- preload B fragments into registers ----
    uint32_t breg[9][KS][2];
    #pragma unroll
    for (int tap = 0; tap < 9; tap++)
        #pragma unroll
        for (int ks = 0; ks < KS; ks++) {
            breg[tap][ks][0] = wT[(tap * W2 + ks * 8 + ci_lo) * CO + ntile * 8 + xA];
            breg[tap][ks][1] = wT[(tap * W2 + ks * 8 + ci_lo + 4) * CO + ntile * 8 + xA];
        }
    const int co_e = ntile * 8 + 2 * ci_lo;
    const float b_lo = bias[co_e], b_hi = bias[co_e + 1];

    __syncthreads();

    float sA = 0.f, qA = 0.f, sB = 0.f, qB = 0.f;
    const size_t chan_stride = HW;

    for (int mi = 0; mi < MT_PER; mi++) {
        int mt = mseg * MT_PER + mi;
        int y = ty0 + mt;
        if (y >= H) break;
        float c0 = 0.f, c1 = 0.f, c2 = 0.f, c3 = 0.f;
        #pragma unroll
        for (int tap = 0; tap < 9; tap++) {
            const int ky = tap / 3, kx = tap - ky * 3;
            #pragma unroll
            for (int ks = 0; ks < KS; ks++) {
                uint32_t a0 = s_in[mt + ky][xA + kx][ks * 8 + ci_lo];
                uint32_t a1 = s_in[mt + ky][xA + 8 + kx][ks * 8 + ci_lo];
                uint32_t a2 = s_in[mt + ky][xA + kx][ks * 8 + ci_lo + 4];
                uint32_t a3 = s_in[mt + ky][xA + 8 + kx][ks * 8 + ci_lo + 4];
                asm volatile(
                    "mma.sync.aligned.m16n8k16.row.col.f32.bf16.bf16.f32 "
                    "{%0,%1,%2,%3}, {%4,%5,%6,%7}, {%8,%9}, {%0,%1,%2,%3};"
                    : "+f"(c0), "+f"(c1), "+f"(c2), "+f"(c3)
                    : "r"(a0), "r"(a1), "r"(a2), "r"(a3),
                      "r"(breg[tap][ks][0]), "r"(breg[tap][ks][1]));
            }
        }
        // epilogue: bias + masked store + stats
        int x_lo = tx0 + xA, x_hi = x_lo + 8;
        size_t base = (((size_t)n * CO + co_e) * H + y) * (size_t)W;
        float v00 = c0 + b_lo, v01 = c1 + b_hi, v10 = c2 + b_lo, v11 = c3 + b_hi;
        if (x_lo < W) {
            out[base + x_lo] = v00;
            out[base + chan_stride + x_lo] = v01;
            sA += v00; qA += v00 * v00; sB += v01; qB += v01 * v01;
        }
        if (x_hi < W) {
            out[base + x_hi] = v10;
            out[base + chan_stride + x_hi] = v11;
            sA += v10; qA += v10 * v10; sB += v11; qB += v11 * v11;
        }
    }

    #pragma unroll
    for (int off = 4; off < 32; off <<= 1) {
        sA += __shfl_xor_sync(0xffffffffu, sA, off);
        qA += __shfl_xor_sync(0xffffffffu, qA, off);
        sB += __shfl_xor_sync(0xffffffffu, sB, off);
        qB += __shfl_xor_sync(0xffffffffu, qB, off);
    }
    if (lane < 4) {
        int slot = (blockIdx.x + blockIdx.z * 977 + warp * 53) & 511;
        atomicAdd(&g_psum  [(layer * 64 + co_e) * 512 + slot], sA);
        atomicAdd(&g_psumsq[(layer * 64 + co_e) * 512 + slot], qA);
        atomicAdd(&g_psum  [(layer * 64 + co_e + 1) * 512 + slot], sB);
        atomicAdd(&g_psumsq[(layer * 64 + co_e + 1) * 512 + slot], qB);
    }
}

// ---------------- layer1 stats: scalar direct conv (CI=1), no store ----------
template<int CI, bool STORE>
__launch_bounds__(128)
__global__ void conv3x3_k(const float* __restrict__ in, const float* __restrict__ w,
                          const float* __restrict__ bias, float* __restrict__ out,
                          int CO, int H, int W, int tiles_x, int layer) {
    __shared__ float s_in[2][18][36];
    __shared__ float s_w[CI * 16 * 9];
    __shared__ float redS[16][4], redQ[16][4];
    const int n   = blockIdx.z;
    const int cog = blockIdx.y;
    const int tile = blockIdx.x;
    const int tx = tile % tiles_x, ty = tile / tiles_x;
    const int tid = threadIdx.x;
    const int warp = tid >> 5, lane = tid & 31;

    for (int i = tid; i < CI * 16 * 9; i += 128)
        s_w[i] = w[(size_t)(cog * 16) * CI * 9 + i];

    const int px = (tid & 7) * 4;
    const int py = tid >> 3;
    const int gx0 = tx * 32 - 1;
    const int gy0 = ty * 16 - 1;

    auto load_tile = [&](int ci, int b) {
        const float* ip = in + ((size_t)n * CI + ci) * (size_t)H * W;
        for (int i = tid; i < 18 * 34; i += 128) {
            int r = i / 34, c = i - r * 34;
            int gy = gy0 + r, gx = gx0 + c;
            float v = 0.f;
            if (gy >= 0 && gy < H && gx >= 0 && gx < W) v = ip[(size_t)gy * W + gx];
            s_in[b][r][c] = v;
        }
    };

    float acc[16][4];
    #pragma unroll
    for (int co = 0; co < 16; co++)
        #pragma unroll
        for (int p = 0; p < 4; p++) acc[co][p] = 0.f;

    load_tile(0, 0);
    __syncthreads();

    for (int ci = 0; ci < CI; ci++) {
        const int cur = ci & 1;
        if (ci + 1 < CI) load_tile(ci + 1, cur ^ 1);

        float iv[3][6];
        #pragma unroll
        for (int ky = 0; ky < 3; ky++)
            #pragma unroll
            for (int j = 0; j < 6; j++)
                iv[ky][j] = s_in[cur][py + ky][px + j];

        #pragma unroll
        for (int co = 0; co < 16; co++) {
            const float* wp = &s_w[(co * CI + ci) * 9];
            #pragma unroll
            for (int ky = 0; ky < 3; ky++)
                #pragma unroll
                for (int kx = 0; kx < 3; kx++) {
                    float wv = wp[ky * 3 + kx];
                    #pragma unroll
                    for (int p = 0; p < 4; p++)
                        acc[co][p] = fmaf(iv[ky][kx + p], wv, acc[co][p]);
                }
        }
        __syncthreads();
    }

    const int y = ty * 16 + py;
    const bool yv = (y < H);
    #pragma unroll
    for (int co = 0; co < 16; co++) {
        int cg = cog * 16 + co;
        float b = bias[cg];
        size_t base = (((size_t)n * CO + cg) * H + y) * (size_t)W;
        float s = 0.f, q = 0.f;
        #pragma unroll
        for (int p = 0; p < 4; p++) {
            int x = tx * 32 + px + p;
            float v = acc[co][p] + b;
            bool valid = yv && (x < W);
            if (STORE && valid) out[base + x] = v;
            if (valid) { s += v; q += v * v; }
        }
        #pragma unroll
        for (int o = 16; o > 0; o >>= 1) {
            s += __shfl_down_sync(0xffffffffu, s, o);
            q += __shfl_down_sync(0xffffffffu, q, o);
        }
        if (lane == 0) { redS[co][warp] = s; redQ[co][warp] = q; }
    }
    __syncthreads();
    if (tid < 16) {
        float S = redS[tid][0] + redS[tid][1] + redS[tid][2] + redS[tid][3];
        float Q = redQ[tid][0] + redQ[tid][1] + redQ[tid][2] + redQ[tid][3];
        int slot = (blockIdx.x + blockIdx.z * 977) & 511;
        int c = cog * 16 + tid;
        atomicAdd(&g_psum[(layer * 64 + c) * 512 + slot], S);
        atomicAdd(&g_psumsq[(layer * 64 + c) * 512 + slot], Q);
    }
}

// ---------------- layer1 fused: conv(1->16) + BN + ReLU + pool2 --------------
__launch_bounds__(128)
__global__ void conv1_pool_k(const float* __restrict__ in, const float* __restrict__ w,
                             const float* __restrict__ bias, float* __restrict__ out) {
    const int H = 224, W = 224;
    __shared__ float s_in[34][35];
    __shared__ float s_w[16 * 9];
    __shared__ float s_a[16], s_t[16];
    const int n = blockIdx.z;
    const int tx = blockIdx.x % 7, ty = blockIdx.x / 7;
    const int tid = threadIdx.x;

    for (int i = tid; i < 144; i += 128) s_w[i] = w[i];
    if (tid < 16) {
        float a = g_scale[tid];
        s_a[tid] = a;
        s_t[tid] = bias[tid] * a + g_shift[tid];
    }
    const int gx0 = tx * 32 - 1, gy0 = ty * 32 - 1;
    const float* ip = in + (size_t)n * H * W;
    for (int i = tid; i < 34 * 34; i += 128) {
        int r = i / 34, c = i % 34;
        int gy = gy0 + r, gx = gx0 + c;
        float v = 0.f;
        if (gy >= 0 && gy < H && gx >= 0 && gx < W) v = ip[(size_t)gy * W + gx];
        s_in[r][c] = v;
    }
    __syncthreads();

    const int pxp = (tid & 7) * 2;
    const int pyp = tid >> 3;
    const int cx = pxp * 2;
    const int cy = pyp * 2;

    float iv[4][6];
    #pragma unroll
    for (int r = 0; r < 4; r++)
        #pragma unroll
        for (int c = 0; c < 6; c++)
            iv[r][c] = s_in[cy + r][cx + c];

    const int gxp = tx * 16 + pxp;
    const int gyp = ty * 16 + pyp;

    #pragma unroll
    for (int co = 0; co < 16; co++) {
        float w0 = s_w[co * 9 + 0], w1 = s_w[co * 9 + 1], w2 = s_w[co * 9 + 2];
        float w3 = s_w[co * 9 + 3], w4 = s_w[co * 9 + 4], w5 = s_w[co * 9 + 5];
        float w6 = s_w[co * 9 + 6], w7 = s_w[co * 9 + 7], w8 = s_w[co * 9 + 8];
        float a = s_a[co], t = s_t[co];
        float v[2][4];
        #pragma unroll
        for (int r = 0; r < 2; r++)
            #pragma unroll
            for (int c = 0; c < 4; c++) {
                float s = iv[r + 0][c + 0] * w0 + iv[r + 0][c + 1] * w1 + iv[r + 0][c + 2] * w2
                        + iv[r + 1][c + 0] * w3 + iv[r + 1][c + 1] * w4 + iv[r + 1][c + 2] * w5
                        + iv[r + 2][c + 0] * w6 + iv[r + 2][c + 1] * w7 + iv[r + 2][c + 2] * w8;
                v[r][c] = fmaf(s, a, t);
            }
        float p0 = fmaxf(fmaxf(v[0][0], v[0][1]), fmaxf(v[1][0], v[1][1]));
        float p1 = fmaxf(fmaxf(v[0][2], v[0][3]), fmaxf(v[1][2], v[1][3]));
        size_t base = (((size_t)n * 16 + co) * 112 + gyp) * (size_t)112 + gxp;
        out[base + 0] = fmaxf(p0, 0.f);
        out[base + 1] = fmaxf(p1, 0.f);
    }
}

// ---------------- BN affine + ReLU + 2x2 maxpool (layers 2,3) ----------------
__global__ void bn_relu_pool_k(const float* __restrict__ in, float* __restrict__ out,
                               int C, int H, int W, long long total) {
    long long idx = (long long)blockIdx.x * blockDim.x + threadIdx.x;
    if (idx >= total) return;
    int W2 = W >> 1, H2 = H >> 1;
    int x2 = (int)(idx % W2);
    long long r = idx / W2;
    int y2 = (int)(r % H2); r /= H2;
    int c  = (int)(r % C);
    int n  = (int)(r / C);
    const float2* p0 = (const float2*)(in + (((size_t)n * C + c) * H + 2 * y2) * (size_t)W) + x2;
    const float2* p1 = (const float2*)((const float*)p0 + W);
    float2 u = *p0, d = *p1;
    float a = g_scale[c], s = g_shift[c];
    float v0 = fmaf(u.x, a, s);
    float v1 = fmaf(u.y, a, s);
    float v2 = fmaf(d.x, a, s);
    float v3 = fmaf(d.y, a, s);
    float m = fmaxf(fmaxf(v0, v1), fmaxf(v2, v3));
    out[idx] = fmaxf(m, 0.f);
}

// ---------------- head: GAP + fc1 + LN + quantum circuit + fc2/fc3 -----------
__global__ void head_k(const float* __restrict__ pooled,   // (B,64,28,28)
                       const float* __restrict__ fc1_w, const float* __restrict__ fc1_b,
                       const float* __restrict__ ln_g,  const float* __restrict__ ln_b,
                       const float* __restrict__ qp,
                       const float* __restrict__ fc2_w, const float* __restrict__ fc2_b,
                       const float* __restrict__ fc3_w, const float* __restrict__ fc3_b,
                       float* __restrict__ out) {
    const int n = blockIdx.x;
    const int tid = threadIdx.x;
    const int warp = tid >> 5, lane = tid & 31;
    __shared__ float chm[64];
    __shared__ float qin[5];
    __shared__ float qres;

    const float* base = pooled + (size_t)n * 64 * 784;
    for (int j = 0; j < 8; j++) {
        int c = warp * 8 + j;
        const float* p = base + (size_t)c * 784;
        float s = 0.f;
        for (int i = lane; i < 784; i += 32) s += p[i];
        #pragma unroll
        for (int o = 16; o > 0; o >>= 1) s += __shfl_down_sync(0xffffffffu, s, o);
        if (lane == 0) chm[c] = s * (1.0f / 784.0f);
    }
    __syncthreads();

    if (tid == 0) {
        float h[5];
        #pragma unroll
        for (int o = 0; o < 5; o++) {
            float s = fc1_b[o];
            for (int i = 0; i < 64; i++) s += chm[i] * fc1_w[i * 5 + o];
            h[o] = s;
        }
        float mu = 0.f;
        #pragma unroll
        for (int o = 0; o < 5; o++) mu += h[o];
        mu *= 0.2f;
        float var = 0.f;
        #pragma unroll
        for (int o = 0; o < 5; o++) { float d = h[o] - mu; var += d * d; }
        var *= 0.2f;
        float r = rsqrtf(var + 1e-5f);
        #pragma unroll
        for (int o = 0; o < 5; o++) qin[o] = ln_g[o] * (h[o] - mu) * r + ln_b[o];
    }
    __syncthreads();

    // 5-qubit statevector: amplitude per lane (warp 0). wire i -> bit (1<<(4-i))
    if (warp == 0) {
        float are = (lane == 0) ? 1.f : 0.f, aim = 0.f;
        const unsigned fm = 0xffffffffu;
        for (int l = 0; l < 3; l++) {
            #pragma unroll
            for (int i = 0; i < 5; i++) {
                int m = 1 << (4 - i);
                float sn, cs; sincosf(qin[i] * 0.5f, &sn, &cs);
                float pre = __shfl_xor_sync(fm, are, m);
                float pim = __shfl_xor_sync(fm, aim, m);
                float nre = cs * are + sn * pim;
                float nim = cs * aim - sn * pre;
                are = nre; aim = nim;
            }
            #pragma unroll
            for (int i = 0; i < 5; i++) {
                int m = 1 << (4 - i);
                float sy, cy; sincosf(qp[l * 10 + i] * 0.5f, &sy, &cy);
                float pre = __shfl_xor_sync(fm, are, m);
                float pim = __shfl_xor_sync(fm, aim, m);
                float sgn = (lane & m) ? sy : -sy;
                float nre = cy * are + sgn * pre;
                float nim = cy * aim + sgn * pim;
                float sz, cz; sincosf(qp[l * 10 + i + 5] * 0.5f, &sz, &cz);
                float zg = (lane & m) ? -sz : sz;
                are = nre * cz + zg * nim;
                aim = nim * cz - zg * nre;
            }
            const int cw[5] = {0, 1, 2, 3, 4};
            const int tw[5] = {1, 2, 3, 4, 0};
            #pragma unroll
            for (int k = 0; k < 5; k++) {
                int mc = 1 << (4 - cw[k]);
                int mt = 1 << (4 - tw[k]);
                int src = (lane & mc) ? (lane ^ mt) : lane;
                are = __shfl_sync(fm, are, src);
                aim = __shfl_sync(fm, aim, src);
            }
        }
        float p = are * are + aim * aim;
        float sgn = (__popc(lane & 28) & 1) ? -1.f : 1.f;
        float v = p * sgn;
        #pragma unroll
        for (int o = 16; o > 0; o >>= 1) v += __shfl_down_sync(fm, v, o);
        if (lane == 0) qres = v;
    }
    __syncthreads();

    if (tid == 0) {
        float q = qres;
        float l0 = fc3_b[0], l1 = fc3_b[1];
        for (int j = 0; j < 32; j++) {
            float h2 = fmaxf(q * fc2_w[j] + fc2_b[j], 0.f);
            l0 += h2 * fc3_w[j * 2 + 0];
            l1 += h2 * fc3_w[j * 2 + 1];
        }
        float mx = fmaxf(l0, l1);
        float lse = mx + logf(expf(l0 - mx) + expf(l1 - mx));
        out[n * 2 + 0] = l0 - lse;
        out[n * 2 + 1] = l1 - lse;
    }
}

// ---------------- host launcher ----------------------------------------------
extern "C" void kernel_launch(void* const* d_in, const int* in_sizes, int n_in,
                              void* d_out, int out_size) {
    const float* x    = (const float*)d_in[0];
    const float* c1w  = (const float*)d_in[1];
    const float* c1b  = (const float*)d_in[2];
    const float* bn1g = (const float*)d_in[3];
    const float* bn1b = (const float*)d_in[4];
    const float* c2w  = (const float*)d_in[5];
    const float* c2b  = (const float*)d_in[6];
    const float* bn2g = (const float*)d_in[7];
    const float* bn2b = (const float*)d_in[8];
    const float* c3w  = (const float*)d_in[9];
    const float* c3b  = (const float*)d_in[10];
    const float* bn3g = (const float*)d_in[11];
    const float* bn3b = (const float*)d_in[12];
    const float* fc1w = (const float*)d_in[13];
    const float* fc1b = (const float*)d_in[14];
    const float* lng  = (const float*)d_in[15];
    const float* lnb  = (const float*)d_in[16];
    const float* qp   = (const float*)d_in[17];
    const float* fc2w = (const float*)d_in[18];
    const float* fc2b = (const float*)d_in[19];
    const float* fc3w = (const float*)d_in[20];
    const float* fc3b = (const float*)d_in[21];
    float* out = (float*)d_out;

    float *conv, *poolA, *poolB;
    uint32_t *wT2, *wT3;
    cudaGetSymbolAddress((void**)&conv,  g_conv);
    cudaGetSymbolAddress((void**)&poolA, g_poolA);
    cudaGetSymbolAddress((void**)&poolB, g_poolB);
    cudaGetSymbolAddress((void**)&wT2, g_wT2);
    cudaGetSymbolAddress((void**)&wT3, g_wT3);

    const int B = 256;

    zero_partials_k<<<(3 * 64 * 512 + 511) / 512, 512>>>();
    wprep_k<<<(9 * 16 * 64 + 255) / 256, 256>>>(c2w, c3w);

    // ---- Layer 1: conv(1->16) @224, scalar stats pass + fused pool pass ----
    {
        int H = 224, W = 224, CO = 16;
        int txs = (W + 31) / 32, tys = (H + 15) / 16;
        conv3x3_k<1, false><<<dim3(txs * tys, 1, B), 128>>>(x, c1w, c1b, nullptr, CO, H, W, txs, 0);
        finalize_k<<<CO, 32>>>(bn1g, bn1b, 0, 1.0 / ((double)B * H * W));
        conv1_pool_k<<<dim3(49, 1, B), 128>>>(x, c1w, c1b, poolA);
    }
    // ---- Layer 2: conv(16->32) @112, BF16 tensor path (tile 16x16, 7x7) ----
    {
        int H = 112, W = 112, CO = 32;
        conv_mma_k<16, 32, 16><<<dim3(7 * 7, 1, B), 256>>>(poolA, wT2, c2b, conv, H, W, 7, 1);
        finalize_k<<<CO, 32>>>(bn2g, bn2b, 1, 1.0 / ((double)B * H * W));
        long long tot = (long long)B * CO * (H / 2) * (W / 2);
        bn_relu_pool_k<<<(unsigned)((tot + 255) / 256), 256>>>(conv, poolB, CO, H, W, tot);
    }
    // ---- Layer 3: conv(32->64) @56, BF16 tensor path (tile 16x14, 4x4) ----
    {
        int H = 56, W = 56, CO = 64;
        conv_mma_k<32, 64, 14><<<dim3(4 * 4, 1, B), 256>>>(poolB, wT3, c3b, conv, H, W, 4, 2);
        finalize_k<<<CO, 32>>>(bn3g, bn3b, 2, 1.0 / ((double)B * H * W));
        long long tot = (long long)B * CO * (H / 2) * (W / 2);
        bn_relu_pool_k<<<(unsigned)((tot + 255) / 256), 256>>>(conv, poolA, CO, H, W, tot);
    }
    // ---- Head ----
    head_k<<<B, 256>>>(poolA, fc1w, fc1b, lng, lnb, qp, fc2w, fc2b, fc3w, fc3b, out);
}